// round 1
// baseline (speedup 1.0000x reference)
#include <cuda_runtime.h>

// ---------------- problem constants ----------------
#define NN 50000      // nodes
#define NE 800000     // edges
#define IC 128        // input channels
#define F1 128        // layer1 out = heads*hid = 4*32
#define H  4          // layer1 heads
#define F2 64         // layer2 out channels

// ---------------- device scratch (no allocations allowed) ----------------
__device__ float g_h1[NN * F1];     // layer1 node features (pre-attention)
__device__ float g_as1[NN * H];
__device__ float g_ad1[NN * H];
__device__ float g_s1[NN * H];      // softmax denominators, layer1
__device__ float g_p1[NE * H];      // exp(logit) per edge, layer1
__device__ float g_out1[NN * F1];   // layer1 aggregated output (then elu'd in place)
__device__ float g_h2[NN * F2];
__device__ float g_as2[NN];
__device__ float g_ad2[NN];
__device__ float g_s2[NN];
__device__ float g_p2[NE];
__device__ int   g_src[NE];
__device__ int   g_dst[NE];

// ---------------- helpers ----------------
__device__ __forceinline__ void red_add_v4(float* addr, float4 v) {
    asm volatile("red.global.add.v4.f32 [%0], {%1,%2,%3,%4};"
                 :: "l"(addr), "f"(v.x), "f"(v.y), "f"(v.z), "f"(v.w) : "memory");
}

__device__ __forceinline__ float lrexp(float t) {
    t = t > 0.f ? t : 0.2f * t;      // LeakyReLU(0.2)
    return __expf(t);
}

// ---------------- edge index conversion (robust to int32/int64) ----------------
__global__ void prep_edges(const int* __restrict__ raw) {
    __shared__ int s_is64;
    if (threadIdx.x == 0) {
        // int64 little-endian: odd 32-bit words are hi-words, always 0 (values < 50000).
        // int32: odd words are random node ids; 64 samples all-zero is impossible in practice.
        int nz = 0;
#pragma unroll
        for (int k = 0; k < 64; k++) nz |= raw[2 * (k * 631) + 1];
        s_is64 = (nz == 0) ? 1 : 0;
    }
    __syncthreads();
    int i = blockIdx.x * blockDim.x + threadIdx.x;
    if (i >= NE) return;
    if (s_is64) {
        g_src[i] = raw[2 * i];
        g_dst[i] = raw[2 * (NE + i)];
    } else {
        g_src[i] = raw[i];
        g_dst[i] = raw[NE + i];
    }
}

// ---------------- zero init ----------------
__global__ void zero_scratch() {
    int i = blockIdx.x * 256 + threadIdx.x;
    int stride = gridDim.x * 256;
    for (int j = i; j < NN * F1; j += stride) g_out1[j] = 0.f;
    for (int j = i; j < NN * H;  j += stride) g_s1[j]   = 0.f;
    for (int j = i; j < NN;      j += stride) g_s2[j]   = 0.f;
}

__global__ void zero_out(float* __restrict__ o) {
    int i = blockIdx.x * blockDim.x + threadIdx.x;
    if (i < NN * F2) o[i] = 0.f;
}

// ---------------- SGEMM: C[M,N] = A[M,K] @ B[K,N] ----------------
// LAYER=1: A = Ain (x), C = g_h1 ; LAYER=2: A = g_out1, C = g_h2
template <int BM, int BN, int BK, int TM, int TN, int LAYER>
__global__ void sgemm(const float* __restrict__ Ain, const float* __restrict__ B,
                      int M, int K) {
    constexpr int NB = BN;                    // BN == N (gridDim.y == 1)
    constexpr int NT = (BM / TM) * (BN / TN);
    const float* A = (LAYER == 1) ? Ain : g_out1;
    float* C       = (LAYER == 1) ? g_h1 : g_h2;

    __shared__ float As[BK][BM];
    __shared__ float Bs[BK][BN];

    const int tid  = threadIdx.x;
    const int trow = tid / (BN / TN);
    const int tcol = tid % (BN / TN);
    const int rowBase = blockIdx.x * BM;

    float acc[TM][TN];
#pragma unroll
    for (int m = 0; m < TM; m++)
#pragma unroll
        for (int n = 0; n < TN; n++) acc[m][n] = 0.f;

    for (int k0 = 0; k0 < K; k0 += BK) {
        for (int i = tid * 4; i < BM * BK; i += NT * 4) {
            int r = i / BK, c = i % BK;       // c in {0,4}
            float4 v = make_float4(0.f, 0.f, 0.f, 0.f);
            int gr = rowBase + r;
            if (gr < M) v = *reinterpret_cast<const float4*>(&A[(long)gr * K + k0 + c]);
            As[c + 0][r] = v.x; As[c + 1][r] = v.y; As[c + 2][r] = v.z; As[c + 3][r] = v.w;
        }
        for (int i = tid * 4; i < BK * BN; i += NT * 4) {
            int r = i / BN, c = i % BN;
            *reinterpret_cast<float4*>(&Bs[r][c]) =
                *reinterpret_cast<const float4*>(&B[(long)(k0 + r) * NB + c]);
        }
        __syncthreads();
#pragma unroll
        for (int k = 0; k < BK; k++) {
            float ra[TM], rb[TN];
#pragma unroll
            for (int m = 0; m < TM; m++) ra[m] = As[k][trow * TM + m];
#pragma unroll
            for (int n = 0; n < TN; n++) rb[n] = Bs[k][tcol * TN + n];
#pragma unroll
            for (int m = 0; m < TM; m++)
#pragma unroll
                for (int n = 0; n < TN; n++) acc[m][n] = fmaf(ra[m], rb[n], acc[m][n]);
        }
        __syncthreads();
    }
#pragma unroll
    for (int m = 0; m < TM; m++) {
        int gr = rowBase + trow * TM + m;
        if (gr < M) {
#pragma unroll
            for (int n = 0; n < TN; n += 4) {
                float4 v = make_float4(acc[m][n], acc[m][n + 1], acc[m][n + 2], acc[m][n + 3]);
                *reinterpret_cast<float4*>(&C[(long)gr * NB + tcol * TN + n]) = v;
            }
        }
    }
}

// ---------------- per-node attention coefficients ----------------
// layer1: one block (128 thr) per node; warp w == head w (32 channels)
__global__ void att1_kernel(const float* __restrict__ att_s, const float* __restrict__ att_d) {
    int n = blockIdx.x;
    int t = threadIdx.x;
    float v = g_h1[n * F1 + t];
    float a = v * att_s[t];
    float b = v * att_d[t];
#pragma unroll
    for (int o = 16; o > 0; o >>= 1) {
        a += __shfl_down_sync(0xffffffffu, a, o);
        b += __shfl_down_sync(0xffffffffu, b, o);
    }
    if ((t & 31) == 0) {
        g_as1[n * H + (t >> 5)] = a;
        g_ad1[n * H + (t >> 5)] = b;
    }
}

// layer2: one warp per node (64 channels -> 2 per lane)
__global__ void att2_kernel(const float* __restrict__ att_s, const float* __restrict__ att_d) {
    int n = blockIdx.x * 4 + (threadIdx.x >> 5);
    int lane = threadIdx.x & 31;
    if (n >= NN) return;
    float v0 = g_h2[n * F2 + lane];
    float v1 = g_h2[n * F2 + 32 + lane];
    float a = v0 * att_s[lane] + v1 * att_s[32 + lane];
    float b = v0 * att_d[lane] + v1 * att_d[32 + lane];
#pragma unroll
    for (int o = 16; o > 0; o >>= 1) {
        a += __shfl_down_sync(0xffffffffu, a, o);
        b += __shfl_down_sync(0xffffffffu, b, o);
    }
    if (lane == 0) { g_as2[n] = a; g_ad2[n] = b; }
}

// ---------------- edge passes, layer 1 ----------------
__global__ void edge_logits1() {
    int e = blockIdx.x * blockDim.x + threadIdx.x;
    if (e >= NE) return;
    int s = g_src[e], d = g_dst[e];
    float4 as = *reinterpret_cast<const float4*>(&g_as1[s * H]);
    float4 ad = *reinterpret_cast<const float4*>(&g_ad1[d * H]);
    float4 p;
    p.x = lrexp(as.x + ad.x);
    p.y = lrexp(as.y + ad.y);
    p.z = lrexp(as.z + ad.z);
    p.w = lrexp(as.w + ad.w);
    *reinterpret_cast<float4*>(&g_p1[e * H]) = p;
    red_add_v4(&g_s1[d * H], p);
}

// one warp per edge: 32 lanes x float4 = 128 floats
__global__ void edge_agg1() {
    int gw   = (blockIdx.x * blockDim.x + threadIdx.x) >> 5;
    int lane = threadIdx.x & 31;
    if (gw >= NE) return;
    int s = g_src[gw], d = g_dst[gw];
    float4 p  = *reinterpret_cast<const float4*>(&g_p1[gw * H]);
    float4 sm = *reinterpret_cast<const float4*>(&g_s1[d * H]);
    float a0 = p.x / (sm.x + 1e-16f);
    float a1 = p.y / (sm.y + 1e-16f);
    float a2 = p.z / (sm.z + 1e-16f);
    float a3 = p.w / (sm.w + 1e-16f);
    float al = lane < 16 ? (lane < 8 ? a0 : a1) : (lane < 24 ? a2 : a3);
    float4 h = *reinterpret_cast<const float4*>(&g_h1[s * F1 + lane * 4]);
    h.x *= al; h.y *= al; h.z *= al; h.w *= al;
    red_add_v4(&g_out1[d * F1 + lane * 4], h);
}

__global__ void elu_bias1(const float* __restrict__ b1) {
    int i = blockIdx.x * blockDim.x + threadIdx.x;
    if (i >= NN * F1) return;
    float v = g_out1[i] + b1[i & (F1 - 1)];
    g_out1[i] = v > 0.f ? v : expm1f(v);
}

// ---------------- edge passes, layer 2 ----------------
__global__ void edge_logits2() {
    int e = blockIdx.x * blockDim.x + threadIdx.x;
    if (e >= NE) return;
    int s = g_src[e], d = g_dst[e];
    float p = lrexp(g_as2[s] + g_ad2[d]);
    g_p2[e] = p;
    atomicAdd(&g_s2[d], p);
}

// half-warp per edge: 16 lanes x float4 = 64 floats
__global__ void edge_agg2(float* __restrict__ out) {
    int gt = blockIdx.x * blockDim.x + threadIdx.x;
    int e  = gt >> 4;
    if (e >= NE) return;
    int q = gt & 15;
    int s = g_src[e], d = g_dst[e];
    float alpha = g_p2[e] / (g_s2[d] + 1e-16f);
    float4 h = *reinterpret_cast<const float4*>(&g_h2[s * F2 + q * 4]);
    h.x *= alpha; h.y *= alpha; h.z *= alpha; h.w *= alpha;
    red_add_v4(&out[d * F2 + q * 4], h);
}

__global__ void bias2_kernel(float* __restrict__ out, const float* __restrict__ b2) {
    int i = blockIdx.x * blockDim.x + threadIdx.x;
    if (i >= NN * F2) return;
    out[i] += b2[i & (F2 - 1)];
}

// ---------------- launch ----------------
extern "C" void kernel_launch(void* const* d_in, const int* in_sizes, int n_in,
                              void* d_out, int out_size) {
    const float* x        = (const float*)d_in[0];
    const int*   ei_raw   = (const int*)d_in[1];   // int32 or int64; detected on device
    const float* W1       = (const float*)d_in[2];
    const float* att_src1 = (const float*)d_in[3];
    const float* att_dst1 = (const float*)d_in[4];
    const float* b1       = (const float*)d_in[5];
    const float* W2       = (const float*)d_in[6];
    const float* att_src2 = (const float*)d_in[7];
    const float* att_dst2 = (const float*)d_in[8];
    const float* b2       = (const float*)d_in[9];
    float* out = (float*)d_out;

    prep_edges<<<(NE + 255) / 256, 256>>>(ei_raw);
    zero_scratch<<<4096, 256>>>();
    zero_out<<<(NN * F2 + 255) / 256, 256>>>(out);

    // ---- layer 1 ----
    sgemm<128, 128, 8, 8, 8, 1><<<(NN + 127) / 128, 256>>>(x, W1, NN, IC);
    att1_kernel<<<NN, 128>>>(att_src1, att_dst1);
    edge_logits1<<<(NE + 255) / 256, 256>>>();
    edge_agg1<<<(NE * 32) / 256, 256>>>();
    elu_bias1<<<(NN * F1 + 255) / 256, 256>>>(b1);

    // ---- layer 2 ----
    sgemm<128, 64, 8, 8, 4, 2><<<(NN + 127) / 128, 256>>>(nullptr, W2, NN, F1);
    att2_kernel<<<(NN + 3) / 4, 128>>>(att_src2, att_dst2);
    edge_logits2<<<(NE + 255) / 256, 256>>>();
    edge_agg2<<<(NE * 16) / 256, 256>>>(out);
    bias2_kernel<<<(NN * F2 + 255) / 256, 256>>>(out, b2);
}

// round 2
// speedup vs baseline: 1.1371x; 1.1371x over previous
#include <cuda_runtime.h>

// ---------------- problem constants ----------------
#define NN 50000      // nodes
#define NE 800000     // edges
#define IC 128        // input channels
#define F1 128        // layer1 out = heads*hid = 4*32
#define H  4          // layer1 heads
#define F2 64         // layer2 out channels

// ---------------- device scratch ----------------
__device__ float g_h1[NN * F1];     // layer1 node features (pre-attention)
__device__ float g_as1[NN * H];
__device__ float g_ad1[NN * H];
__device__ float g_s1[NN * H];      // sum of p per dst node, layer1
__device__ float g_out1[NN * F1];   // layer1 UNNORMALIZED aggregate sum(p*h)
__device__ float g_h2[NN * F2];
__device__ float g_as2[NN];
__device__ float g_ad2[NN];
__device__ float g_s2[NN];
__device__ int   g_src[NE];
__device__ int   g_dst[NE];

// ---------------- helpers ----------------
__device__ __forceinline__ void red_add_v4(float* addr, float4 v) {
    asm volatile("red.global.add.v4.f32 [%0], {%1,%2,%3,%4};"
                 :: "l"(addr), "f"(v.x), "f"(v.y), "f"(v.z), "f"(v.w) : "memory");
}

__device__ __forceinline__ float lrexp(float t) {
    t = t > 0.f ? t : 0.2f * t;      // LeakyReLU(0.2)
    return __expf(t);
}

// ---------------- edge index conversion (robust to int32/int64) ----------------
__global__ void prep_edges(const int* __restrict__ raw) {
    __shared__ int s_is64;
    if (threadIdx.x == 0) {
        int nz = 0;
#pragma unroll
        for (int k = 0; k < 64; k++) nz |= raw[2 * (k * 631) + 1];
        s_is64 = (nz == 0) ? 1 : 0;
    }
    __syncthreads();
    int i = blockIdx.x * blockDim.x + threadIdx.x;
    if (i >= NE) return;
    if (s_is64) {
        g_src[i] = raw[2 * i];
        g_dst[i] = raw[2 * (NE + i)];
    } else {
        g_src[i] = raw[i];
        g_dst[i] = raw[NE + i];
    }
}

// ---------------- zero init ----------------
__global__ void zero_scratch() {
    int i = blockIdx.x * 256 + threadIdx.x;
    int stride = gridDim.x * 256;
    for (int j = i; j < NN * F1; j += stride) g_out1[j] = 0.f;
    for (int j = i; j < NN * H;  j += stride) g_s1[j]   = 0.f;
    for (int j = i; j < NN;      j += stride) g_s2[j]   = 0.f;
}

__global__ void zero_out(float* __restrict__ o) {
    int i = blockIdx.x * blockDim.x + threadIdx.x;
    if (i < NN * F2) o[i] = 0.f;
}

// ---------------- SGEMM: C[M,BN] = A[M,128] @ B[128,BN], double-buffered ----------------
// LAYER=1: A = x (raw),     C = g_h1
// LAYER=2: A = g_out1 with fused normalize + bias + ELU,  C = g_h2
template <int BM, int BN, int BK, int TM, int TN, int LAYER>
__global__ void __launch_bounds__((BM / TM) * (BN / TN), 2)
sgemm(const float* __restrict__ Ain, const float* __restrict__ B,
      const float* __restrict__ bias, int M) {
    constexpr int K = 128;
    constexpr int NT = (BM / TM) * (BN / TN);
    constexpr int A_IT = BM * BK / (4 * NT);
    constexpr int B_IT = BK * BN / (4 * NT);
    const float* A = (LAYER == 1) ? Ain : g_out1;
    float* C       = (LAYER == 1) ? g_h1 : g_h2;

    __shared__ float As[2][BK][BM];   // transposed: As[k][m]
    __shared__ float Bs[2][BK][BN];

    const int tid  = threadIdx.x;
    const int trow = tid / (BN / TN);
    const int tcol = tid % (BN / TN);
    const int rowBase = blockIdx.x * BM;

    float4 aReg[A_IT], bReg[B_IT];

    auto gload = [&](int k0) {
#pragma unroll
        for (int it = 0; it < A_IT; it++) {
            int i = (tid + it * NT) * 4;
            int r = i / BK, c = i % BK;
            int gr = rowBase + r;
            float4 v = make_float4(0.f, 0.f, 0.f, 0.f);
            if (gr < M) {
                v = *reinterpret_cast<const float4*>(&A[(long)gr * K + k0 + c]);
                if (LAYER == 2) {
                    // channels k0+c .. k0+c+3 share one head ((k0+c) % 4 == 0, aligned)
                    float inv = 1.f / (g_s1[gr * H + ((k0 + c) >> 5)] + 1e-16f);
                    float4 bb = *reinterpret_cast<const float4*>(&bias[k0 + c]);
                    v.x = v.x * inv + bb.x; v.x = v.x > 0.f ? v.x : expm1f(v.x);
                    v.y = v.y * inv + bb.y; v.y = v.y > 0.f ? v.y : expm1f(v.y);
                    v.z = v.z * inv + bb.z; v.z = v.z > 0.f ? v.z : expm1f(v.z);
                    v.w = v.w * inv + bb.w; v.w = v.w > 0.f ? v.w : expm1f(v.w);
                }
            }
            aReg[it] = v;
        }
#pragma unroll
        for (int it = 0; it < B_IT; it++) {
            int i = (tid + it * NT) * 4;
            int r = i / BN, c = i % BN;
            bReg[it] = *reinterpret_cast<const float4*>(&B[(long)(k0 + r) * BN + c]);
        }
    };

    auto sstore = [&](int buf) {
#pragma unroll
        for (int it = 0; it < A_IT; it++) {
            int i = (tid + it * NT) * 4;
            int r = i / BK, c = i % BK;
            As[buf][c + 0][r] = aReg[it].x;
            As[buf][c + 1][r] = aReg[it].y;
            As[buf][c + 2][r] = aReg[it].z;
            As[buf][c + 3][r] = aReg[it].w;
        }
#pragma unroll
        for (int it = 0; it < B_IT; it++) {
            int i = (tid + it * NT) * 4;
            int r = i / BN, c = i % BN;
            *reinterpret_cast<float4*>(&Bs[buf][r][c]) = bReg[it];
        }
    };

    float acc[TM][TN];
#pragma unroll
    for (int m = 0; m < TM; m++)
#pragma unroll
        for (int n = 0; n < TN; n++) acc[m][n] = 0.f;

    auto compute = [&](int buf) {
#pragma unroll
        for (int k = 0; k < BK; k++) {
            float ra[TM], rb[TN];
#pragma unroll
            for (int m = 0; m < TM; m += 4)
                *reinterpret_cast<float4*>(&ra[m]) =
                    *reinterpret_cast<const float4*>(&As[buf][k][trow * TM + m]);
#pragma unroll
            for (int n = 0; n < TN; n += 4)
                *reinterpret_cast<float4*>(&rb[n]) =
                    *reinterpret_cast<const float4*>(&Bs[buf][k][tcol * TN + n]);
#pragma unroll
            for (int m = 0; m < TM; m++)
#pragma unroll
                for (int n = 0; n < TN; n++)
                    acc[m][n] = fmaf(ra[m], rb[n], acc[m][n]);
        }
    };

    gload(0);
    sstore(0);
    __syncthreads();
    int buf = 0;
    for (int k0 = BK; k0 < K; k0 += BK) {
        gload(k0);
        compute(buf);
        sstore(buf ^ 1);
        __syncthreads();
        buf ^= 1;
    }
    compute(buf);

#pragma unroll
    for (int m = 0; m < TM; m++) {
        int gr = rowBase + trow * TM + m;
        if (gr < M) {
#pragma unroll
            for (int n = 0; n < TN; n += 4) {
                float4 v = make_float4(acc[m][n], acc[m][n + 1], acc[m][n + 2], acc[m][n + 3]);
                *reinterpret_cast<float4*>(&C[(long)gr * BN + tcol * TN + n]) = v;
            }
        }
    }
}

// ---------------- per-node attention coefficients ----------------
__global__ void att1_kernel(const float* __restrict__ att_s, const float* __restrict__ att_d) {
    int n = blockIdx.x;
    int t = threadIdx.x;
    float v = g_h1[n * F1 + t];
    float a = v * att_s[t];
    float b = v * att_d[t];
#pragma unroll
    for (int o = 16; o > 0; o >>= 1) {
        a += __shfl_down_sync(0xffffffffu, a, o);
        b += __shfl_down_sync(0xffffffffu, b, o);
    }
    if ((t & 31) == 0) {
        g_as1[n * H + (t >> 5)] = a;
        g_ad1[n * H + (t >> 5)] = b;
    }
}

__global__ void att2_kernel(const float* __restrict__ att_s, const float* __restrict__ att_d) {
    int n = blockIdx.x * 4 + (threadIdx.x >> 5);
    int lane = threadIdx.x & 31;
    if (n >= NN) return;
    float v0 = g_h2[n * F2 + lane];
    float v1 = g_h2[n * F2 + 32 + lane];
    float a = v0 * att_s[lane] + v1 * att_s[32 + lane];
    float b = v0 * att_d[lane] + v1 * att_d[32 + lane];
#pragma unroll
    for (int o = 16; o > 0; o >>= 1) {
        a += __shfl_down_sync(0xffffffffu, a, o);
        b += __shfl_down_sync(0xffffffffu, b, o);
    }
    if (lane == 0) { g_as2[n] = a; g_ad2[n] = b; }
}

// ---------------- fused edge pass, layer 1 (one warp per edge) ----------------
// Scatters UNNORMALIZED p*h into g_out1 and p into g_s1; normalization is fused
// into the layer-2 GEMM A-load.
__global__ void edge1() {
    int gw   = (blockIdx.x * blockDim.x + threadIdx.x) >> 5;
    int lane = threadIdx.x & 31;
    if (gw >= NE) return;
    int s = g_src[gw], d = g_dst[gw];
    float p = 0.f;
    if (lane < H) p = lrexp(g_as1[s * H + lane] + g_ad1[d * H + lane]);
    float al = __shfl_sync(0xffffffffu, p, lane >> 3);   // head = lane/8
    float4 h = *reinterpret_cast<const float4*>(&g_h1[s * F1 + lane * 4]);
    h.x *= al; h.y *= al; h.z *= al; h.w *= al;
    red_add_v4(&g_out1[d * F1 + lane * 4], h);
    float p0 = __shfl_sync(0xffffffffu, p, 0);
    float p1 = __shfl_sync(0xffffffffu, p, 1);
    float p2 = __shfl_sync(0xffffffffu, p, 2);
    float p3 = __shfl_sync(0xffffffffu, p, 3);
    if (lane == 0) red_add_v4(&g_s1[d * H], make_float4(p0, p1, p2, p3));
}

// ---------------- fused edge pass, layer 2 (16 lanes per edge) ----------------
__global__ void edge2(float* __restrict__ out) {
    int gt = blockIdx.x * blockDim.x + threadIdx.x;
    int e  = gt >> 4;
    if (e >= NE) return;
    int q = gt & 15;
    int lane = threadIdx.x & 31;
    int s = g_src[e], d = g_dst[e];
    float p = 0.f;
    if (q == 0) p = lrexp(g_as2[s] + g_ad2[d]);
    p = __shfl_sync(0xffffffffu, p, lane & 16);          // broadcast within 16-group
    float4 h = *reinterpret_cast<const float4*>(&g_h2[s * F2 + q * 4]);
    h.x *= p; h.y *= p; h.z *= p; h.w *= p;
    red_add_v4(&out[d * F2 + q * 4], h);
    if (q == 0) atomicAdd(&g_s2[d], p);
}

// ---------------- final normalize + bias ----------------
__global__ void norm2_kernel(float* __restrict__ out, const float* __restrict__ b2) {
    int i = blockIdx.x * blockDim.x + threadIdx.x;
    if (i >= NN * F2) return;
    int n = i >> 6, c = i & 63;
    out[i] = out[i] / (g_s2[n] + 1e-16f) + b2[c];
}

// ---------------- launch ----------------
extern "C" void kernel_launch(void* const* d_in, const int* in_sizes, int n_in,
                              void* d_out, int out_size) {
    const float* x        = (const float*)d_in[0];
    const int*   ei_raw   = (const int*)d_in[1];
    const float* W1       = (const float*)d_in[2];
    const float* att_src1 = (const float*)d_in[3];
    const float* att_dst1 = (const float*)d_in[4];
    const float* b1       = (const float*)d_in[5];
    const float* W2       = (const float*)d_in[6];
    const float* att_src2 = (const float*)d_in[7];
    const float* att_dst2 = (const float*)d_in[8];
    const float* b2       = (const float*)d_in[9];
    float* out = (float*)d_out;

    prep_edges<<<(NE + 255) / 256, 256>>>(ei_raw);
    zero_scratch<<<4096, 256>>>();
    zero_out<<<(NN * F2 + 255) / 256, 256>>>(out);

    // ---- layer 1 ----
    sgemm<128, 128, 16, 8, 8, 1><<<(NN + 127) / 128, 256>>>(x, W1, nullptr, NN);
    att1_kernel<<<NN, 128>>>(att_src1, att_dst1);
    edge1<<<(NE * 32) / 256, 256>>>();

    // ---- layer 2 (norm+bias+elu fused into A-load) ----
    sgemm<128, 64, 16, 8, 4, 2><<<(NN + 127) / 128, 256>>>(nullptr, W2, b1, NN);
    att2_kernel<<<(NN + 3) / 4, 128>>>(att_src2, att_dst2);
    edge2<<<(NE * 16) / 256, 256>>>(out);
    norm2_kernel<<<(NN * F2 + 255) / 256, 256>>>(out, b2);
}

// round 3
// speedup vs baseline: 1.3000x; 1.1433x over previous
#include <cuda_runtime.h>

// ---------------- problem constants ----------------
#define NN 50000      // nodes
#define NE 800000     // edges
#define IC 128        // input channels
#define F1 128        // layer1 out = heads*hid = 4*32
#define H  4          // layer1 heads
#define F2 64         // layer2 out channels

// ---------------- device scratch ----------------
__device__ float g_h1[NN * F1];     // layer1 node features (pre-attention)
__device__ float g_as1[NN * H];
__device__ float g_ad1[NN * H];
__device__ float g_out1[NN * F1];   // layer1 output, normalized + bias + elu
__device__ float g_h2[NN * F2];
__device__ float g_as2[NN];
__device__ float g_ad2[NN];
__device__ int   g_src[NE];
__device__ int   g_dst[NE];
__device__ int   g_cnt[NN];         // degree histogram / scatter counters
__device__ int   g_rowptr[NN + 1];
__device__ int   g_csrc[NE];        // src ids sorted by dst (CSR)

// ---------------- helpers ----------------
__device__ __forceinline__ float lrexp(float t) {
    t = t > 0.f ? t : 0.2f * t;      // LeakyReLU(0.2)
    return __expf(t);
}

// ---------------- CSR build ----------------
__global__ void zero_cnt() {
    int i = blockIdx.x * blockDim.x + threadIdx.x;
    if (i < NN) g_cnt[i] = 0;
}

// edge index conversion (robust to int32/int64) + dst histogram
__global__ void prep_edges(const int* __restrict__ raw) {
    __shared__ int s_is64;
    if (threadIdx.x == 0) {
        int nz = 0;
#pragma unroll
        for (int k = 0; k < 64; k++) nz |= raw[2 * (k * 631) + 1];
        s_is64 = (nz == 0) ? 1 : 0;
    }
    __syncthreads();
    int i = blockIdx.x * blockDim.x + threadIdx.x;
    if (i >= NE) return;
    int s, d;
    if (s_is64) {
        s = raw[2 * i];
        d = raw[2 * (NE + i)];
    } else {
        s = raw[i];
        d = raw[NE + i];
    }
    g_src[i] = s;
    g_dst[i] = d;
    atomicAdd(&g_cnt[d], 1);
}

// single-block exclusive scan over 50k degrees -> rowptr; resets cnt to 0
__global__ void scan_rowptr() {
    __shared__ int ssum[1024];
    const int t = threadIdx.x;
    const int CH = (NN + 1023) / 1024;   // 49
    const int base = t * CH;
    int local = 0;
    for (int i = 0; i < CH; i++) {
        int idx = base + i;
        if (idx < NN) local += g_cnt[idx];
    }
    ssum[t] = local;
    __syncthreads();
    for (int off = 1; off < 1024; off <<= 1) {
        int v = (t >= off) ? ssum[t - off] : 0;
        __syncthreads();
        ssum[t] += v;
        __syncthreads();
    }
    int run = (t > 0) ? ssum[t - 1] : 0;   // exclusive prefix
    for (int i = 0; i < CH; i++) {
        int idx = base + i;
        if (idx < NN) {
            int c = g_cnt[idx];
            g_rowptr[idx] = run;
            run += c;
            g_cnt[idx] = 0;
        }
    }
    if (t == 1023) g_rowptr[NN] = run;     // == NE
}

__global__ void scatter_edges() {
    int i = blockIdx.x * blockDim.x + threadIdx.x;
    if (i >= NE) return;
    int d = g_dst[i];
    int pos = g_rowptr[d] + atomicAdd(&g_cnt[d], 1);
    g_csrc[pos] = g_src[i];
}

// ---------------- SGEMM: C[M,BN] = A[M,128] @ B[128,BN], double-buffered ----------------
template <int BM, int BN, int BK, int TM, int TN, int LAYER>
__global__ void __launch_bounds__((BM / TM) * (BN / TN), 2)
sgemm(const float* __restrict__ Ain, const float* __restrict__ B, int M) {
    constexpr int K = 128;
    constexpr int NT = (BM / TM) * (BN / TN);
    constexpr int A_IT = BM * BK / (4 * NT);
    constexpr int B_IT = BK * BN / (4 * NT);
    const float* A = (LAYER == 1) ? Ain : g_out1;
    float* C       = (LAYER == 1) ? g_h1 : g_h2;

    __shared__ float As[2][BK][BM];   // transposed: As[k][m]
    __shared__ float Bs[2][BK][BN];

    const int tid  = threadIdx.x;
    const int trow = tid / (BN / TN);
    const int tcol = tid % (BN / TN);
    const int rowBase = blockIdx.x * BM;

    float4 aReg[A_IT], bReg[B_IT];

    auto gload = [&](int k0) {
#pragma unroll
        for (int it = 0; it < A_IT; it++) {
            int i = (tid + it * NT) * 4;
            int r = i / BK, c = i % BK;
            int gr = rowBase + r;
            float4 v = make_float4(0.f, 0.f, 0.f, 0.f);
            if (gr < M) v = *reinterpret_cast<const float4*>(&A[(long)gr * K + k0 + c]);
            aReg[it] = v;
        }
#pragma unroll
        for (int it = 0; it < B_IT; it++) {
            int i = (tid + it * NT) * 4;
            int r = i / BN, c = i % BN;
            bReg[it] = *reinterpret_cast<const float4*>(&B[(long)(k0 + r) * BN + c]);
        }
    };

    auto sstore = [&](int buf) {
#pragma unroll
        for (int it = 0; it < A_IT; it++) {
            int i = (tid + it * NT) * 4;
            int r = i / BK, c = i % BK;
            As[buf][c + 0][r] = aReg[it].x;
            As[buf][c + 1][r] = aReg[it].y;
            As[buf][c + 2][r] = aReg[it].z;
            As[buf][c + 3][r] = aReg[it].w;
        }
#pragma unroll
        for (int it = 0; it < B_IT; it++) {
            int i = (tid + it * NT) * 4;
            int r = i / BN, c = i % BN;
            *reinterpret_cast<float4*>(&Bs[buf][r][c]) = bReg[it];
        }
    };

    float acc[TM][TN];
#pragma unroll
    for (int m = 0; m < TM; m++)
#pragma unroll
        for (int n = 0; n < TN; n++) acc[m][n] = 0.f;

    auto compute = [&](int buf) {
#pragma unroll
        for (int k = 0; k < BK; k++) {
            float ra[TM], rb[TN];
#pragma unroll
            for (int m = 0; m < TM; m += 4)
                *reinterpret_cast<float4*>(&ra[m]) =
                    *reinterpret_cast<const float4*>(&As[buf][k][trow * TM + m]);
#pragma unroll
            for (int n = 0; n < TN; n += 4)
                *reinterpret_cast<float4*>(&rb[n]) =
                    *reinterpret_cast<const float4*>(&Bs[buf][k][tcol * TN + n]);
#pragma unroll
            for (int m = 0; m < TM; m++)
#pragma unroll
                for (int n = 0; n < TN; n++)
                    acc[m][n] = fmaf(ra[m], rb[n], acc[m][n]);
        }
    };

    gload(0);
    sstore(0);
    __syncthreads();
    int buf = 0;
    for (int k0 = BK; k0 < K; k0 += BK) {
        gload(k0);
        compute(buf);
        sstore(buf ^ 1);
        __syncthreads();
        buf ^= 1;
    }
    compute(buf);

#pragma unroll
    for (int m = 0; m < TM; m++) {
        int gr = rowBase + trow * TM + m;
        if (gr < M) {
#pragma unroll
            for (int n = 0; n < TN; n += 4) {
                float4 v = make_float4(acc[m][n], acc[m][n + 1], acc[m][n + 2], acc[m][n + 3]);
                *reinterpret_cast<float4*>(&C[(long)gr * BN + tcol * TN + n]) = v;
            }
        }
    }
}

// ---------------- per-node attention coefficients ----------------
__global__ void att1_kernel(const float* __restrict__ att_s, const float* __restrict__ att_d) {
    int n = blockIdx.x;
    int t = threadIdx.x;
    float v = g_h1[n * F1 + t];
    float a = v * att_s[t];
    float b = v * att_d[t];
#pragma unroll
    for (int o = 16; o > 0; o >>= 1) {
        a += __shfl_down_sync(0xffffffffu, a, o);
        b += __shfl_down_sync(0xffffffffu, b, o);
    }
    if ((t & 31) == 0) {
        g_as1[n * H + (t >> 5)] = a;
        g_ad1[n * H + (t >> 5)] = b;
    }
}

__global__ void att2_kernel(const float* __restrict__ att_s, const float* __restrict__ att_d) {
    int n = blockIdx.x * 4 + (threadIdx.x >> 5);
    int lane = threadIdx.x & 31;
    if (n >= NN) return;
    float v0 = g_h2[n * F2 + lane];
    float v1 = g_h2[n * F2 + 32 + lane];
    float a = v0 * att_s[lane] + v1 * att_s[32 + lane];
    float b = v0 * att_d[lane] + v1 * att_d[32 + lane];
#pragma unroll
    for (int o = 16; o > 0; o >>= 1) {
        a += __shfl_down_sync(0xffffffffu, a, o);
        b += __shfl_down_sync(0xffffffffu, b, o);
    }
    if (lane == 0) { g_as2[n] = a; g_ad2[n] = b; }
}

// ---------------- layer-1 aggregation: one warp per dst node ----------------
// Single pass: acc = sum(p * h1[src]), sump = sum(p); out = elu(acc/sump + b1).
__global__ void agg1(const float* __restrict__ b1) {
    int n    = (blockIdx.x * blockDim.x + threadIdx.x) >> 5;
    int lane = threadIdx.x & 31;
    if (n >= NN) return;
    const int beg = g_rowptr[n], end = g_rowptr[n + 1];
    const int head = lane >> 3;
    const float ad = g_ad1[n * H + head];

    float sump = 0.f;
    float4 acc = make_float4(0.f, 0.f, 0.f, 0.f);

    for (int e0 = beg; e0 < end; e0 += 32) {
        int m = min(32, end - e0);
        int s_all = (lane < m) ? g_csrc[e0 + lane] : 0;
        for (int j = 0; j < m; j++) {
            int s = __shfl_sync(0xffffffffu, s_all, j);
            float p = lrexp(g_as1[s * H + head] + ad);
            sump += p;
            float4 h = *reinterpret_cast<const float4*>(&g_h1[s * F1 + lane * 4]);
            acc.x = fmaf(p, h.x, acc.x);
            acc.y = fmaf(p, h.y, acc.y);
            acc.z = fmaf(p, h.z, acc.z);
            acc.w = fmaf(p, h.w, acc.w);
        }
    }
    float inv = 1.f / (sump + 1e-16f);
    float4 bb = *reinterpret_cast<const float4*>(&b1[lane * 4]);
    float4 o;
    o.x = acc.x * inv + bb.x; o.x = o.x > 0.f ? o.x : expm1f(o.x);
    o.y = acc.y * inv + bb.y; o.y = o.y > 0.f ? o.y : expm1f(o.y);
    o.z = acc.z * inv + bb.z; o.z = o.z > 0.f ? o.z : expm1f(o.z);
    o.w = acc.w * inv + bb.w; o.w = o.w > 0.f ? o.w : expm1f(o.w);
    *reinterpret_cast<float4*>(&g_out1[n * F1 + lane * 4]) = o;
}

// ---------------- layer-2 aggregation: one warp per dst node ----------------
__global__ void agg2(float* __restrict__ out, const float* __restrict__ b2) {
    int n    = (blockIdx.x * blockDim.x + threadIdx.x) >> 5;
    int lane = threadIdx.x & 31;
    if (n >= NN) return;
    const int beg = g_rowptr[n], end = g_rowptr[n + 1];
    const float ad = g_ad2[n];

    float sump = 0.f;
    float2 acc = make_float2(0.f, 0.f);

    for (int e0 = beg; e0 < end; e0 += 32) {
        int m = min(32, end - e0);
        int s_all = (lane < m) ? g_csrc[e0 + lane] : 0;
        for (int j = 0; j < m; j++) {
            int s = __shfl_sync(0xffffffffu, s_all, j);
            float p = lrexp(g_as2[s] + ad);
            sump += p;
            float2 h = *reinterpret_cast<const float2*>(&g_h2[s * F2 + lane * 2]);
            acc.x = fmaf(p, h.x, acc.x);
            acc.y = fmaf(p, h.y, acc.y);
        }
    }
    float inv = 1.f / (sump + 1e-16f);
    float2 o;
    o.x = acc.x * inv + b2[lane * 2];
    o.y = acc.y * inv + b2[lane * 2 + 1];
    *reinterpret_cast<float2*>(&out[n * F2 + lane * 2]) = o;
}

// ---------------- launch ----------------
extern "C" void kernel_launch(void* const* d_in, const int* in_sizes, int n_in,
                              void* d_out, int out_size) {
    const float* x        = (const float*)d_in[0];
    const int*   ei_raw   = (const int*)d_in[1];
    const float* W1       = (const float*)d_in[2];
    const float* att_src1 = (const float*)d_in[3];
    const float* att_dst1 = (const float*)d_in[4];
    const float* b1       = (const float*)d_in[5];
    const float* W2       = (const float*)d_in[6];
    const float* att_src2 = (const float*)d_in[7];
    const float* att_dst2 = (const float*)d_in[8];
    const float* b2       = (const float*)d_in[9];
    float* out = (float*)d_out;

    // ---- CSR build ----
    zero_cnt<<<(NN + 255) / 256, 256>>>();
    prep_edges<<<(NE + 255) / 256, 256>>>(ei_raw);
    scan_rowptr<<<1, 1024>>>();
    scatter_edges<<<(NE + 255) / 256, 256>>>();

    // ---- layer 1 ----
    sgemm<128, 128, 16, 8, 8, 1><<<(NN + 127) / 128, 256>>>(x, W1, NN);
    att1_kernel<<<NN, 128>>>(att_src1, att_dst1);
    agg1<<<(NN * 32 + 255) / 256, 256>>>(b1);

    // ---- layer 2 ----
    sgemm<128, 64, 16, 8, 4, 2><<<(NN + 127) / 128, 256>>>(nullptr, W2, NN);
    att2_kernel<<<(NN + 3) / 4, 128>>>(att_src2, att_dst2);
    agg2<<<(NN * 32 + 255) / 256, 256>>>(out, b2);
}

// round 4
// speedup vs baseline: 1.3927x; 1.0713x over previous
#include <cuda_runtime.h>

// ---------------- problem constants ----------------
#define NN 50000      // nodes
#define NE 800000     // edges
#define IC 128        // input channels
#define F1 128        // layer1 out = heads*hid = 4*32
#define H  4          // layer1 heads
#define F2 64         // layer2 out channels

// ---------------- device scratch ----------------
__device__ float g_h1[NN * F1];     // layer1 node features (pre-attention)
__device__ float g_as1[NN * H];
__device__ float g_ad1[NN * H];
__device__ float g_out1[NN * F1];   // layer1 output, normalized + bias + elu
__device__ float g_h2[NN * F2];
__device__ float g_as2[NN];
__device__ float g_ad2[NN];
__device__ int   g_cnt[NN];         // degree histogram / scatter counters
__device__ int   g_rowptr[NN + 1];
__device__ int   g_csrc[NE];        // src ids sorted by dst (CSR)

// ---------------- helpers ----------------
__device__ __forceinline__ float lrexp(float t) {
    t = t > 0.f ? t : 0.2f * t;      // LeakyReLU(0.2)
    return __expf(t);
}

__device__ __forceinline__ int detect_is64(const int* __restrict__ raw) {
    // int64 little-endian: odd 32-bit words are hi-words, always 0 (ids < 50000).
    int nz = 0;
#pragma unroll
    for (int k = 0; k < 64; k++) nz |= raw[2 * (k * 631) + 1];
    return (nz == 0) ? 1 : 0;
}

// ---------------- CSR build ----------------
__global__ void zero_cnt() {
    int i = blockIdx.x * blockDim.x + threadIdx.x;
    if (i < NN) g_cnt[i] = 0;
}

__global__ void hist_edges(const int* __restrict__ raw) {
    __shared__ int s_is64;
    if (threadIdx.x == 0) s_is64 = detect_is64(raw);
    __syncthreads();
    int i = blockIdx.x * blockDim.x + threadIdx.x;
    if (i >= NE) return;
    int d = s_is64 ? reinterpret_cast<const int2*>(raw)[NE + i].x : raw[NE + i];
    atomicAdd(&g_cnt[d], 1);
}

// single-block exclusive scan over 50k degrees -> rowptr; resets cnt to 0
__global__ void scan_rowptr() {
    __shared__ int ssum[1024];
    const int t = threadIdx.x;
    const int CH = (NN + 1023) / 1024;   // 49
    const int base = t * CH;
    int local = 0;
    for (int i = 0; i < CH; i++) {
        int idx = base + i;
        if (idx < NN) local += g_cnt[idx];
    }
    ssum[t] = local;
    __syncthreads();
    for (int off = 1; off < 1024; off <<= 1) {
        int v = (t >= off) ? ssum[t - off] : 0;
        __syncthreads();
        ssum[t] += v;
        __syncthreads();
    }
    int run = (t > 0) ? ssum[t - 1] : 0;   // exclusive prefix
    for (int i = 0; i < CH; i++) {
        int idx = base + i;
        if (idx < NN) {
            int c = g_cnt[idx];
            g_rowptr[idx] = run;
            run += c;
            g_cnt[idx] = 0;
        }
    }
    if (t == 1023) g_rowptr[NN] = run;     // == NE
}

__global__ void scatter_edges(const int* __restrict__ raw) {
    __shared__ int s_is64;
    if (threadIdx.x == 0) s_is64 = detect_is64(raw);
    __syncthreads();
    int i = blockIdx.x * blockDim.x + threadIdx.x;
    if (i >= NE) return;
    int s, d;
    if (s_is64) {
        s = reinterpret_cast<const int2*>(raw)[i].x;
        d = reinterpret_cast<const int2*>(raw)[NE + i].x;
    } else {
        s = raw[i];
        d = raw[NE + i];
    }
    int pos = g_rowptr[d] + atomicAdd(&g_cnt[d], 1);
    g_csrc[pos] = s;
}

// ---------------- SGEMM + fused attention-coefficient epilogue ----------------
// LAYER=1: C = g_h1 [NN,128]; epilogue -> g_as1/g_ad1 (per head, 4 heads of 32 ch)
// LAYER=2: C = g_h2 [NN,64];  epilogue -> g_as2/g_ad2 (single head)
template <int BM, int BN, int BK, int TM, int TN, int LAYER>
__global__ void __launch_bounds__((BM / TM) * (BN / TN), 2)
sgemm(const float* __restrict__ Ain, const float* __restrict__ B,
      const float* __restrict__ attS, const float* __restrict__ attD, int M) {
    constexpr int K = 128;
    constexpr int NT = (BM / TM) * (BN / TN);
    constexpr int A_IT = BM * BK / (4 * NT);
    constexpr int B_IT = BK * BN / (4 * NT);
    const float* A = (LAYER == 1) ? Ain : g_out1;
    float* C       = (LAYER == 1) ? g_h1 : g_h2;

    __shared__ __align__(16) float As[2][BK][BM];   // transposed: As[k][m]
    __shared__ __align__(16) float Bs[2][BK][BN];

    const int tid  = threadIdx.x;
    const int trow = tid / (BN / TN);
    const int tcol = tid % (BN / TN);
    const int rowBase = blockIdx.x * BM;

    float4 aReg[A_IT], bReg[B_IT];

    auto gload = [&](int k0) {
#pragma unroll
        for (int it = 0; it < A_IT; it++) {
            int i = (tid + it * NT) * 4;
            int r = i / BK, c = i % BK;
            int gr = rowBase + r;
            float4 v = make_float4(0.f, 0.f, 0.f, 0.f);
            if (gr < M) v = *reinterpret_cast<const float4*>(&A[(long)gr * K + k0 + c]);
            aReg[it] = v;
        }
#pragma unroll
        for (int it = 0; it < B_IT; it++) {
            int i = (tid + it * NT) * 4;
            int r = i / BN, c = i % BN;
            bReg[it] = *reinterpret_cast<const float4*>(&B[(long)(k0 + r) * BN + c]);
        }
    };

    auto sstore = [&](int buf) {
#pragma unroll
        for (int it = 0; it < A_IT; it++) {
            int i = (tid + it * NT) * 4;
            int r = i / BK, c = i % BK;
            As[buf][c + 0][r] = aReg[it].x;
            As[buf][c + 1][r] = aReg[it].y;
            As[buf][c + 2][r] = aReg[it].z;
            As[buf][c + 3][r] = aReg[it].w;
        }
#pragma unroll
        for (int it = 0; it < B_IT; it++) {
            int i = (tid + it * NT) * 4;
            int r = i / BN, c = i % BN;
            *reinterpret_cast<float4*>(&Bs[buf][r][c]) = bReg[it];
        }
    };

    float acc[TM][TN];
#pragma unroll
    for (int m = 0; m < TM; m++)
#pragma unroll
        for (int n = 0; n < TN; n++) acc[m][n] = 0.f;

    auto compute = [&](int buf) {
#pragma unroll
        for (int k = 0; k < BK; k++) {
            float ra[TM], rb[TN];
#pragma unroll
            for (int m = 0; m < TM; m += 4)
                *reinterpret_cast<float4*>(&ra[m]) =
                    *reinterpret_cast<const float4*>(&As[buf][k][trow * TM + m]);
#pragma unroll
            for (int n = 0; n < TN; n += 4)
                *reinterpret_cast<float4*>(&rb[n]) =
                    *reinterpret_cast<const float4*>(&Bs[buf][k][tcol * TN + n]);
#pragma unroll
            for (int m = 0; m < TM; m++)
#pragma unroll
                for (int n = 0; n < TN; n++)
                    acc[m][n] = fmaf(ra[m], rb[n], acc[m][n]);
        }
    };

    gload(0);
    sstore(0);
    __syncthreads();
    int buf = 0;
    for (int k0 = BK; k0 < K; k0 += BK) {
        gload(k0);
        compute(buf);
        sstore(buf ^ 1);
        __syncthreads();
        buf ^= 1;
    }
    compute(buf);

    // ---- write C tile ----
#pragma unroll
    for (int m = 0; m < TM; m++) {
        int gr = rowBase + trow * TM + m;
        if (gr < M) {
#pragma unroll
            for (int n = 0; n < TN; n += 4) {
                float4 v = make_float4(acc[m][n], acc[m][n + 1], acc[m][n + 2], acc[m][n + 3]);
                *reinterpret_cast<float4*>(&C[(long)gr * BN + tcol * TN + n]) = v;
            }
        }
    }

    // ---- fused attention epilogue ----
    float asr[TN], adr[TN];
#pragma unroll
    for (int n = 0; n < TN; n++) {
        asr[n] = attS[tcol * TN + n];
        adr[n] = attD[tcol * TN + n];
    }
    float pa[TM], pd[TM];
#pragma unroll
    for (int m = 0; m < TM; m++) {
        float a = 0.f, b = 0.f;
#pragma unroll
        for (int n = 0; n < TN; n++) {
            a = fmaf(acc[m][n], asr[n], a);
            b = fmaf(acc[m][n], adr[n], b);
        }
        if (LAYER == 1) {
            // sum across 4 tcols of same head (adjacent lanes, group of 4)
            a += __shfl_down_sync(0xffffffffu, a, 2);
            a += __shfl_down_sync(0xffffffffu, a, 1);
            b += __shfl_down_sync(0xffffffffu, b, 2);
            b += __shfl_down_sync(0xffffffffu, b, 1);
        } else {
            // sum across 16 tcols (group of 16 aligned lanes)
            a += __shfl_down_sync(0xffffffffu, a, 8);
            a += __shfl_down_sync(0xffffffffu, a, 4);
            a += __shfl_down_sync(0xffffffffu, a, 2);
            a += __shfl_down_sync(0xffffffffu, a, 1);
            b += __shfl_down_sync(0xffffffffu, b, 8);
            b += __shfl_down_sync(0xffffffffu, b, 4);
            b += __shfl_down_sync(0xffffffffu, b, 2);
            b += __shfl_down_sync(0xffffffffu, b, 1);
        }
        pa[m] = a;
        pd[m] = b;
    }

    float* sA = &Bs[0][0][0];                     // reuse smem (BM*H floats max)
    float* sD = sA + BM * H;
    __syncthreads();                              // compute done everywhere

    if (LAYER == 1) {
        if ((tcol & 3) == 0) {
            int head = tcol >> 2;
#pragma unroll
            for (int m = 0; m < TM; m++) {
                sA[(trow * TM + m) * H + head] = pa[m];
                sD[(trow * TM + m) * H + head] = pd[m];
            }
        }
        __syncthreads();
        if (tid < BM) {
            int gr = rowBase + tid;
            if (gr < M) {
                *reinterpret_cast<float4*>(&g_as1[gr * H]) =
                    *reinterpret_cast<const float4*>(&sA[tid * H]);
                *reinterpret_cast<float4*>(&g_ad1[gr * H]) =
                    *reinterpret_cast<const float4*>(&sD[tid * H]);
            }
        }
    } else {
        if (tcol == 0) {
#pragma unroll
            for (int m = 0; m < TM; m++) {
                sA[trow * TM + m] = pa[m];
                sD[trow * TM + m] = pd[m];
            }
        }
        __syncthreads();
        if (tid < BM) {
            int gr = rowBase + tid;
            if (gr < M) {
                g_as2[gr] = sA[tid];
                g_ad2[gr] = sD[tid];
            }
        }
    }
}

// ---------------- layer-1 aggregation: one warp per dst node ----------------
// Single pass: acc = sum(p * h1[src]), sump = sum(p); out = elu(acc/sump + b1).
__global__ void agg1(const float* __restrict__ b1) {
    int n    = (blockIdx.x * blockDim.x + threadIdx.x) >> 5;
    int lane = threadIdx.x & 31;
    if (n >= NN) return;
    const int beg = g_rowptr[n], end = g_rowptr[n + 1];
    const int head = lane >> 3;
    const float ad = g_ad1[n * H + head];

    float sump = 0.f;
    float4 acc = make_float4(0.f, 0.f, 0.f, 0.f);

    for (int e0 = beg; e0 < end; e0 += 32) {
        int m = min(32, end - e0);
        int s_all = (lane < m) ? g_csrc[e0 + lane] : 0;
        for (int j = 0; j < m; j++) {
            int s = __shfl_sync(0xffffffffu, s_all, j);
            float p = lrexp(g_as1[s * H + head] + ad);
            sump += p;
            float4 h = *reinterpret_cast<const float4*>(&g_h1[s * F1 + lane * 4]);
            acc.x = fmaf(p, h.x, acc.x);
            acc.y = fmaf(p, h.y, acc.y);
            acc.z = fmaf(p, h.z, acc.z);
            acc.w = fmaf(p, h.w, acc.w);
        }
    }
    float inv = 1.f / (sump + 1e-16f);
    float4 bb = *reinterpret_cast<const float4*>(&b1[lane * 4]);
    float4 o;
    o.x = acc.x * inv + bb.x; o.x = o.x > 0.f ? o.x : expm1f(o.x);
    o.y = acc.y * inv + bb.y; o.y = o.y > 0.f ? o.y : expm1f(o.y);
    o.z = acc.z * inv + bb.z; o.z = o.z > 0.f ? o.z : expm1f(o.z);
    o.w = acc.w * inv + bb.w; o.w = o.w > 0.f ? o.w : expm1f(o.w);
    *reinterpret_cast<float4*>(&g_out1[n * F1 + lane * 4]) = o;
}

// ---------------- layer-2 aggregation: one warp per dst node ----------------
__global__ void agg2(float* __restrict__ out, const float* __restrict__ b2) {
    int n    = (blockIdx.x * blockDim.x + threadIdx.x) >> 5;
    int lane = threadIdx.x & 31;
    if (n >= NN) return;
    const int beg = g_rowptr[n], end = g_rowptr[n + 1];
    const float ad = g_ad2[n];

    float sump = 0.f;
    float2 acc = make_float2(0.f, 0.f);

    for (int e0 = beg; e0 < end; e0 += 32) {
        int m = min(32, end - e0);
        int s_all = (lane < m) ? g_csrc[e0 + lane] : 0;
        for (int j = 0; j < m; j++) {
            int s = __shfl_sync(0xffffffffu, s_all, j);
            float p = lrexp(g_as2[s] + ad);
            sump += p;
            float2 h = *reinterpret_cast<const float2*>(&g_h2[s * F2 + lane * 2]);
            acc.x = fmaf(p, h.x, acc.x);
            acc.y = fmaf(p, h.y, acc.y);
        }
    }
    float inv = 1.f / (sump + 1e-16f);
    float2 o;
    o.x = acc.x * inv + b2[lane * 2];
    o.y = acc.y * inv + b2[lane * 2 + 1];
    *reinterpret_cast<float2*>(&out[n * F2 + lane * 2]) = o;
}

// ---------------- launch ----------------
extern "C" void kernel_launch(void* const* d_in, const int* in_sizes, int n_in,
                              void* d_out, int out_size) {
    const float* x        = (const float*)d_in[0];
    const int*   ei_raw   = (const int*)d_in[1];
    const float* W1       = (const float*)d_in[2];
    const float* att_src1 = (const float*)d_in[3];
    const float* att_dst1 = (const float*)d_in[4];
    const float* b1       = (const float*)d_in[5];
    const float* W2       = (const float*)d_in[6];
    const float* att_src2 = (const float*)d_in[7];
    const float* att_dst2 = (const float*)d_in[8];
    const float* b2       = (const float*)d_in[9];
    float* out = (float*)d_out;

    // one-time stream/event setup (first call is the uncaptured correctness run)
    static cudaStream_t sCsr = nullptr;
    static cudaEvent_t evFork = nullptr, evJoin = nullptr;
    if (sCsr == nullptr) {
        cudaStreamCreateWithFlags(&sCsr, cudaStreamNonBlocking);
        cudaEventCreateWithFlags(&evFork, cudaEventDisableTiming);
        cudaEventCreateWithFlags(&evJoin, cudaEventDisableTiming);
    }

    // ---- fork: CSR build chain on sCsr, concurrent with layer-1 GEMM ----
    cudaEventRecord(evFork, 0);
    cudaStreamWaitEvent(sCsr, evFork, 0);
    zero_cnt<<<(NN + 255) / 256, 256, 0, sCsr>>>();
    hist_edges<<<(NE + 255) / 256, 256, 0, sCsr>>>(ei_raw);
    scan_rowptr<<<1, 1024, 0, sCsr>>>();
    scatter_edges<<<(NE + 255) / 256, 256, 0, sCsr>>>(ei_raw);
    cudaEventRecord(evJoin, sCsr);

    // ---- layer 1 GEMM + att epilogue (default stream) ----
    sgemm<128, 128, 16, 8, 8, 1><<<(NN + 127) / 128, 256>>>(x, W1, att_src1, att_dst1, NN);

    // ---- join, then aggregation ----
    cudaStreamWaitEvent(0, evJoin, 0);
    agg1<<<(NN * 32 + 255) / 256, 256>>>(b1);

    // ---- layer 2 ----
    sgemm<128, 64, 16, 8, 4, 2><<<(NN + 127) / 128, 256>>>(nullptr, W2, att_src2, att_dst2, NN);
    agg2<<<(NN * 32 + 255) / 256, 256>>>(out, b2);
}

// round 5
// speedup vs baseline: 1.4289x; 1.0260x over previous
#include <cuda_runtime.h>

// ---------------- problem constants ----------------
#define NN 50000      // nodes
#define NE 800000     // edges
#define IC 128        // input channels
#define F1 128        // layer1 out = heads*hid = 4*32
#define H  4          // layer1 heads
#define F2 64         // layer2 out channels

// ---------------- device scratch ----------------
__device__ float g_h1[NN * F1];     // layer1 node features (pre-attention)
__device__ float g_as1[NN * H];
__device__ float g_ad1[NN * H];
__device__ float g_out1[NN * F1];   // layer1 output, normalized + bias + elu
__device__ float g_h2[NN * F2];
__device__ float g_as2[NN];
__device__ float g_ad2[NN];
__device__ int   g_cnt[NN];         // degree histogram / scatter counters
__device__ int   g_rowptr[NN + 1];
__device__ int   g_csrc[NE];        // src ids sorted by dst (CSR)

// ---------------- helpers ----------------
__device__ __forceinline__ float lrexp(float t) {
    t = t > 0.f ? t : 0.2f * t;      // LeakyReLU(0.2)
    return __expf(t);
}

__device__ __forceinline__ int detect_is64(const int* __restrict__ raw) {
    // int64 little-endian: odd 32-bit words are hi-words, always 0 (ids < 50000).
    int nz = 0;
#pragma unroll
    for (int k = 0; k < 64; k++) nz |= raw[2 * (k * 631) + 1];
    return (nz == 0) ? 1 : 0;
}

// ---------------- CSR build ----------------
__global__ void zero_cnt() {
    int i = blockIdx.x * blockDim.x + threadIdx.x;
    if (i < NN) g_cnt[i] = 0;
}

__global__ void hist_edges(const int* __restrict__ raw) {
    __shared__ int s_is64;
    if (threadIdx.x == 0) s_is64 = detect_is64(raw);
    __syncthreads();
    int i = blockIdx.x * blockDim.x + threadIdx.x;
    if (i >= NE) return;
    int d = s_is64 ? reinterpret_cast<const int2*>(raw)[NE + i].x : raw[NE + i];
    atomicAdd(&g_cnt[d], 1);
}

// single-block exclusive scan over 50k degrees -> rowptr; resets cnt to 0
__global__ void scan_rowptr() {
    __shared__ int ssum[1024];
    const int t = threadIdx.x;
    const int CH = (NN + 1023) / 1024;   // 49
    const int base = t * CH;
    int local = 0;
    for (int i = 0; i < CH; i++) {
        int idx = base + i;
        if (idx < NN) local += g_cnt[idx];
    }
    ssum[t] = local;
    __syncthreads();
    for (int off = 1; off < 1024; off <<= 1) {
        int v = (t >= off) ? ssum[t - off] : 0;
        __syncthreads();
        ssum[t] += v;
        __syncthreads();
    }
    int run = (t > 0) ? ssum[t - 1] : 0;   // exclusive prefix
    for (int i = 0; i < CH; i++) {
        int idx = base + i;
        if (idx < NN) {
            int c = g_cnt[idx];
            g_rowptr[idx] = run;
            run += c;
            g_cnt[idx] = 0;
        }
    }
    if (t == 1023) g_rowptr[NN] = run;     // == NE
}

__global__ void scatter_edges(const int* __restrict__ raw) {
    __shared__ int s_is64;
    if (threadIdx.x == 0) s_is64 = detect_is64(raw);
    __syncthreads();
    int i = blockIdx.x * blockDim.x + threadIdx.x;
    if (i >= NE) return;
    int s, d;
    if (s_is64) {
        s = reinterpret_cast<const int2*>(raw)[i].x;
        d = reinterpret_cast<const int2*>(raw)[NE + i].x;
    } else {
        s = raw[i];
        d = raw[NE + i];
    }
    int pos = g_rowptr[d] + atomicAdd(&g_cnt[d], 1);
    g_csrc[pos] = s;
}

// ---------------- SGEMM + fused attention-coefficient epilogue ----------------
template <int BM, int BN, int BK, int TM, int TN, int LAYER>
__global__ void __launch_bounds__((BM / TM) * (BN / TN), 2)
sgemm(const float* __restrict__ Ain, const float* __restrict__ B,
      const float* __restrict__ attS, const float* __restrict__ attD, int M) {
    constexpr int K = 128;
    constexpr int NT = (BM / TM) * (BN / TN);
    constexpr int A_IT = BM * BK / (4 * NT);
    constexpr int B_IT = BK * BN / (4 * NT);
    const float* A = (LAYER == 1) ? Ain : g_out1;
    float* C       = (LAYER == 1) ? g_h1 : g_h2;

    __shared__ __align__(16) float As[2][BK][BM];   // transposed: As[k][m]
    __shared__ __align__(16) float Bs[2][BK][BN];

    const int tid  = threadIdx.x;
    const int trow = tid / (BN / TN);
    const int tcol = tid % (BN / TN);
    const int rowBase = blockIdx.x * BM;

    float4 aReg[A_IT], bReg[B_IT];

    auto gload = [&](int k0) {
#pragma unroll
        for (int it = 0; it < A_IT; it++) {
            int i = (tid + it * NT) * 4;
            int r = i / BK, c = i % BK;
            int gr = rowBase + r;
            float4 v = make_float4(0.f, 0.f, 0.f, 0.f);
            if (gr < M) v = *reinterpret_cast<const float4*>(&A[(long)gr * K + k0 + c]);
            aReg[it] = v;
        }
#pragma unroll
        for (int it = 0; it < B_IT; it++) {
            int i = (tid + it * NT) * 4;
            int r = i / BN, c = i % BN;
            bReg[it] = *reinterpret_cast<const float4*>(&B[(long)(k0 + r) * BN + c]);
        }
    };

    auto sstore = [&](int buf) {
#pragma unroll
        for (int it = 0; it < A_IT; it++) {
            int i = (tid + it * NT) * 4;
            int r = i / BK, c = i % BK;
            As[buf][c + 0][r] = aReg[it].x;
            As[buf][c + 1][r] = aReg[it].y;
            As[buf][c + 2][r] = aReg[it].z;
            As[buf][c + 3][r] = aReg[it].w;
        }
#pragma unroll
        for (int it = 0; it < B_IT; it++) {
            int i = (tid + it * NT) * 4;
            int r = i / BN, c = i % BN;
            *reinterpret_cast<float4*>(&Bs[buf][r][c]) = bReg[it];
        }
    };

    float acc[TM][TN];
#pragma unroll
    for (int m = 0; m < TM; m++)
#pragma unroll
        for (int n = 0; n < TN; n++) acc[m][n] = 0.f;

    auto compute = [&](int buf) {
#pragma unroll
        for (int k = 0; k < BK; k++) {
            float ra[TM], rb[TN];
#pragma unroll
            for (int m = 0; m < TM; m += 4)
                *reinterpret_cast<float4*>(&ra[m]) =
                    *reinterpret_cast<const float4*>(&As[buf][k][trow * TM + m]);
#pragma unroll
            for (int n = 0; n < TN; n += 4)
                *reinterpret_cast<float4*>(&rb[n]) =
                    *reinterpret_cast<const float4*>(&Bs[buf][k][tcol * TN + n]);
#pragma unroll
            for (int m = 0; m < TM; m++)
#pragma unroll
                for (int n = 0; n < TN; n++)
                    acc[m][n] = fmaf(ra[m], rb[n], acc[m][n]);
        }
    };

    gload(0);
    sstore(0);
    __syncthreads();
    int buf = 0;
    for (int k0 = BK; k0 < K; k0 += BK) {
        gload(k0);
        compute(buf);
        sstore(buf ^ 1);
        __syncthreads();
        buf ^= 1;
    }
    compute(buf);

    // ---- write C tile ----
#pragma unroll
    for (int m = 0; m < TM; m++) {
        int gr = rowBase + trow * TM + m;
        if (gr < M) {
#pragma unroll
            for (int n = 0; n < TN; n += 4) {
                float4 v = make_float4(acc[m][n], acc[m][n + 1], acc[m][n + 2], acc[m][n + 3]);
                *reinterpret_cast<float4*>(&C[(long)gr * BN + tcol * TN + n]) = v;
            }
        }
    }

    // ---- fused attention epilogue ----
    float asr[TN], adr[TN];
#pragma unroll
    for (int n = 0; n < TN; n++) {
        asr[n] = attS[tcol * TN + n];
        adr[n] = attD[tcol * TN + n];
    }
    float pa[TM], pd[TM];
#pragma unroll
    for (int m = 0; m < TM; m++) {
        float a = 0.f, b = 0.f;
#pragma unroll
        for (int n = 0; n < TN; n++) {
            a = fmaf(acc[m][n], asr[n], a);
            b = fmaf(acc[m][n], adr[n], b);
        }
        if (LAYER == 1) {
            a += __shfl_down_sync(0xffffffffu, a, 2);
            a += __shfl_down_sync(0xffffffffu, a, 1);
            b += __shfl_down_sync(0xffffffffu, b, 2);
            b += __shfl_down_sync(0xffffffffu, b, 1);
        } else {
            a += __shfl_down_sync(0xffffffffu, a, 8);
            a += __shfl_down_sync(0xffffffffu, a, 4);
            a += __shfl_down_sync(0xffffffffu, a, 2);
            a += __shfl_down_sync(0xffffffffu, a, 1);
            b += __shfl_down_sync(0xffffffffu, b, 8);
            b += __shfl_down_sync(0xffffffffu, b, 4);
            b += __shfl_down_sync(0xffffffffu, b, 2);
            b += __shfl_down_sync(0xffffffffu, b, 1);
        }
        pa[m] = a;
        pd[m] = b;
    }

    float* sA = &Bs[0][0][0];
    float* sD = sA + BM * H;
    __syncthreads();

    if (LAYER == 1) {
        if ((tcol & 3) == 0) {
            int head = tcol >> 2;
#pragma unroll
            for (int m = 0; m < TM; m++) {
                sA[(trow * TM + m) * H + head] = pa[m];
                sD[(trow * TM + m) * H + head] = pd[m];
            }
        }
        __syncthreads();
        if (tid < BM) {
            int gr = rowBase + tid;
            if (gr < M) {
                *reinterpret_cast<float4*>(&g_as1[gr * H]) =
                    *reinterpret_cast<const float4*>(&sA[tid * H]);
                *reinterpret_cast<float4*>(&g_ad1[gr * H]) =
                    *reinterpret_cast<const float4*>(&sD[tid * H]);
            }
        }
    } else {
        if (tcol == 0) {
#pragma unroll
            for (int m = 0; m < TM; m++) {
                sA[trow * TM + m] = pa[m];
                sD[trow * TM + m] = pd[m];
            }
        }
        __syncthreads();
        if (tid < BM) {
            int gr = rowBase + tid;
            if (gr < M) {
                g_as2[gr] = sA[tid];
                g_ad2[gr] = sD[tid];
            }
        }
    }
}

// ---------------- layer-1 aggregation: one warp per dst node ----------------
// Phase A: lane-parallel p computation (no serial exp/load chain).
// Phase B: unroll-4 gather with 4 independent accumulators (MLP=4).
__global__ void __launch_bounds__(256) agg1(const float* __restrict__ b1) {
    __shared__ __align__(16) float sp[8][32][4];   // staged p per head
    __shared__ int ssrc[8][32];
    const int wid  = threadIdx.x >> 5;
    const int lane = threadIdx.x & 31;
    const int n    = (blockIdx.x * blockDim.x + threadIdx.x) >> 5;
    if (n >= NN) return;
    const int beg = g_rowptr[n], end = g_rowptr[n + 1];
    const int head = lane >> 3;
    const float4 ad = *reinterpret_cast<const float4*>(&g_ad1[n * H]);

    float4 sumv = make_float4(0.f, 0.f, 0.f, 0.f);
    float4 acc0 = make_float4(0.f, 0.f, 0.f, 0.f);
    float4 acc1 = make_float4(0.f, 0.f, 0.f, 0.f);
    float4 acc2 = make_float4(0.f, 0.f, 0.f, 0.f);
    float4 acc3 = make_float4(0.f, 0.f, 0.f, 0.f);

    for (int e0 = beg; e0 < end; e0 += 32) {
        const int m = min(32, end - e0);
        // ---- phase A: lane j handles edge e0+j ----
        float4 p4 = make_float4(0.f, 0.f, 0.f, 0.f);
        int s = 0;
        if (lane < m) {
            s = g_csrc[e0 + lane];
            float4 as = *reinterpret_cast<const float4*>(&g_as1[s * H]);
            p4.x = lrexp(as.x + ad.x);
            p4.y = lrexp(as.y + ad.y);
            p4.z = lrexp(as.z + ad.z);
            p4.w = lrexp(as.w + ad.w);
        }
        sumv.x += p4.x; sumv.y += p4.y; sumv.z += p4.z; sumv.w += p4.w;
        *reinterpret_cast<float4*>(&sp[wid][lane][0]) = p4;
        ssrc[wid][lane] = s;
        __syncwarp();
        // ---- phase B: unroll-4 gather ----
        int j = 0;
        for (; j + 4 <= m; j += 4) {
            int s0 = ssrc[wid][j + 0];
            int s1 = ssrc[wid][j + 1];
            int s2 = ssrc[wid][j + 2];
            int s3 = ssrc[wid][j + 3];
            float a0 = sp[wid][j + 0][head];
            float a1 = sp[wid][j + 1][head];
            float a2 = sp[wid][j + 2][head];
            float a3 = sp[wid][j + 3][head];
            float4 h0 = *reinterpret_cast<const float4*>(&g_h1[s0 * F1 + lane * 4]);
            float4 h1v = *reinterpret_cast<const float4*>(&g_h1[s1 * F1 + lane * 4]);
            float4 h2v = *reinterpret_cast<const float4*>(&g_h1[s2 * F1 + lane * 4]);
            float4 h3 = *reinterpret_cast<const float4*>(&g_h1[s3 * F1 + lane * 4]);
            acc0.x = fmaf(a0, h0.x, acc0.x); acc0.y = fmaf(a0, h0.y, acc0.y);
            acc0.z = fmaf(a0, h0.z, acc0.z); acc0.w = fmaf(a0, h0.w, acc0.w);
            acc1.x = fmaf(a1, h1v.x, acc1.x); acc1.y = fmaf(a1, h1v.y, acc1.y);
            acc1.z = fmaf(a1, h1v.z, acc1.z); acc1.w = fmaf(a1, h1v.w, acc1.w);
            acc2.x = fmaf(a2, h2v.x, acc2.x); acc2.y = fmaf(a2, h2v.y, acc2.y);
            acc2.z = fmaf(a2, h2v.z, acc2.z); acc2.w = fmaf(a2, h2v.w, acc2.w);
            acc3.x = fmaf(a3, h3.x, acc3.x); acc3.y = fmaf(a3, h3.y, acc3.y);
            acc3.z = fmaf(a3, h3.z, acc3.z); acc3.w = fmaf(a3, h3.w, acc3.w);
        }
        for (; j < m; j++) {
            int sj = ssrc[wid][j];
            float aj = sp[wid][j][head];
            float4 h = *reinterpret_cast<const float4*>(&g_h1[sj * F1 + lane * 4]);
            acc0.x = fmaf(aj, h.x, acc0.x); acc0.y = fmaf(aj, h.y, acc0.y);
            acc0.z = fmaf(aj, h.z, acc0.z); acc0.w = fmaf(aj, h.w, acc0.w);
        }
        __syncwarp();
    }

    float4 acc;
    acc.x = (acc0.x + acc1.x) + (acc2.x + acc3.x);
    acc.y = (acc0.y + acc1.y) + (acc2.y + acc3.y);
    acc.z = (acc0.z + acc1.z) + (acc2.z + acc3.z);
    acc.w = (acc0.w + acc1.w) + (acc2.w + acc3.w);

    // reduce sumv across the warp (each component = one head's sum)
#pragma unroll
    for (int o = 16; o > 0; o >>= 1) {
        sumv.x += __shfl_xor_sync(0xffffffffu, sumv.x, o);
        sumv.y += __shfl_xor_sync(0xffffffffu, sumv.y, o);
        sumv.z += __shfl_xor_sync(0xffffffffu, sumv.z, o);
        sumv.w += __shfl_xor_sync(0xffffffffu, sumv.w, o);
    }
    float sump = head == 0 ? sumv.x : head == 1 ? sumv.y : head == 2 ? sumv.z : sumv.w;
    float inv = 1.f / (sump + 1e-16f);
    float4 bb = *reinterpret_cast<const float4*>(&b1[lane * 4]);
    float4 o;
    o.x = acc.x * inv + bb.x; o.x = o.x > 0.f ? o.x : expm1f(o.x);
    o.y = acc.y * inv + bb.y; o.y = o.y > 0.f ? o.y : expm1f(o.y);
    o.z = acc.z * inv + bb.z; o.z = o.z > 0.f ? o.z : expm1f(o.z);
    o.w = acc.w * inv + bb.w; o.w = o.w > 0.f ? o.w : expm1f(o.w);
    *reinterpret_cast<float4*>(&g_out1[n * F1 + lane * 4]) = o;
}

// ---------------- layer-2 aggregation: one warp per dst node ----------------
__global__ void __launch_bounds__(256) agg2(float* __restrict__ out, const float* __restrict__ b2) {
    __shared__ float sp[8][32];
    __shared__ int ssrc[8][32];
    const int wid  = threadIdx.x >> 5;
    const int lane = threadIdx.x & 31;
    const int n    = (blockIdx.x * blockDim.x + threadIdx.x) >> 5;
    if (n >= NN) return;
    const int beg = g_rowptr[n], end = g_rowptr[n + 1];
    const float ad = g_ad2[n];

    float sump = 0.f;
    float2 acc0 = make_float2(0.f, 0.f);
    float2 acc1 = make_float2(0.f, 0.f);
    float2 acc2 = make_float2(0.f, 0.f);
    float2 acc3 = make_float2(0.f, 0.f);

    for (int e0 = beg; e0 < end; e0 += 32) {
        const int m = min(32, end - e0);
        float p = 0.f;
        int s = 0;
        if (lane < m) {
            s = g_csrc[e0 + lane];
            p = lrexp(g_as2[s] + ad);
        }
        sump += p;
        sp[wid][lane] = p;
        ssrc[wid][lane] = s;
        __syncwarp();
        int j = 0;
        for (; j + 4 <= m; j += 4) {
            int s0 = ssrc[wid][j + 0];
            int s1 = ssrc[wid][j + 1];
            int s2 = ssrc[wid][j + 2];
            int s3 = ssrc[wid][j + 3];
            float a0 = sp[wid][j + 0];
            float a1 = sp[wid][j + 1];
            float a2 = sp[wid][j + 2];
            float a3 = sp[wid][j + 3];
            float2 h0 = *reinterpret_cast<const float2*>(&g_h2[s0 * F2 + lane * 2]);
            float2 h1v = *reinterpret_cast<const float2*>(&g_h2[s1 * F2 + lane * 2]);
            float2 h2v = *reinterpret_cast<const float2*>(&g_h2[s2 * F2 + lane * 2]);
            float2 h3 = *reinterpret_cast<const float2*>(&g_h2[s3 * F2 + lane * 2]);
            acc0.x = fmaf(a0, h0.x, acc0.x); acc0.y = fmaf(a0, h0.y, acc0.y);
            acc1.x = fmaf(a1, h1v.x, acc1.x); acc1.y = fmaf(a1, h1v.y, acc1.y);
            acc2.x = fmaf(a2, h2v.x, acc2.x); acc2.y = fmaf(a2, h2v.y, acc2.y);
            acc3.x = fmaf(a3, h3.x, acc3.x); acc3.y = fmaf(a3, h3.y, acc3.y);
        }
        for (; j < m; j++) {
            int sj = ssrc[wid][j];
            float aj = sp[wid][j];
            float2 h = *reinterpret_cast<const float2*>(&g_h2[sj * F2 + lane * 2]);
            acc0.x = fmaf(aj, h.x, acc0.x); acc0.y = fmaf(aj, h.y, acc0.y);
        }
        __syncwarp();
    }

    float2 acc;
    acc.x = (acc0.x + acc1.x) + (acc2.x + acc3.x);
    acc.y = (acc0.y + acc1.y) + (acc2.y + acc3.y);
#pragma unroll
    for (int o = 16; o > 0; o >>= 1)
        sump += __shfl_xor_sync(0xffffffffu, sump, o);
    float inv = 1.f / (sump + 1e-16f);
    float2 o;
    o.x = acc.x * inv + b2[lane * 2];
    o.y = acc.y * inv + b2[lane * 2 + 1];
    *reinterpret_cast<float2*>(&out[n * F2 + lane * 2]) = o;
}

// ---------------- launch ----------------
extern "C" void kernel_launch(void* const* d_in, const int* in_sizes, int n_in,
                              void* d_out, int out_size) {
    const float* x        = (const float*)d_in[0];
    const int*   ei_raw   = (const int*)d_in[1];
    const float* W1       = (const float*)d_in[2];
    const float* att_src1 = (const float*)d_in[3];
    const float* att_dst1 = (const float*)d_in[4];
    const float* b1       = (const float*)d_in[5];
    const float* W2       = (const float*)d_in[6];
    const float* att_src2 = (const float*)d_in[7];
    const float* att_dst2 = (const float*)d_in[8];
    const float* b2       = (const float*)d_in[9];
    float* out = (float*)d_out;

    static cudaStream_t sCsr = nullptr;
    static cudaEvent_t evFork = nullptr, evJoin = nullptr;
    if (sCsr == nullptr) {
        cudaStreamCreateWithFlags(&sCsr, cudaStreamNonBlocking);
        cudaEventCreateWithFlags(&evFork, cudaEventDisableTiming);
        cudaEventCreateWithFlags(&evJoin, cudaEventDisableTiming);
    }

    // ---- fork: CSR build chain on sCsr, concurrent with layer-1 GEMM ----
    cudaEventRecord(evFork, 0);
    cudaStreamWaitEvent(sCsr, evFork, 0);
    zero_cnt<<<(NN + 255) / 256, 256, 0, sCsr>>>();
    hist_edges<<<(NE + 255) / 256, 256, 0, sCsr>>>(ei_raw);
    scan_rowptr<<<1, 1024, 0, sCsr>>>();
    scatter_edges<<<(NE + 255) / 256, 256, 0, sCsr>>>(ei_raw);
    cudaEventRecord(evJoin, sCsr);

    // ---- layer 1 GEMM + att epilogue (default stream) ----
    sgemm<128, 128, 16, 8, 8, 1><<<(NN + 127) / 128, 256>>>(x, W1, att_src1, att_dst1, NN);

    // ---- join, then aggregation ----
    cudaStreamWaitEvent(0, evJoin, 0);
    agg1<<<(NN * 32 + 255) / 256, 256>>>(b1);

    // ---- layer 2 ----
    sgemm<128, 64, 16, 8, 4, 2><<<(NN + 127) / 128, 256>>>(nullptr, W2, att_src2, att_dst2, NN);
    agg2<<<(NN * 32 + 255) / 256, 256>>>(out, b2);
}

// round 6
// speedup vs baseline: 1.6180x; 1.1324x over previous
#include <cuda_runtime.h>
#include <cuda_fp16.h>

// ---------------- problem constants ----------------
#define NN 50000      // nodes
#define NE 800000     // edges
#define IC 128        // input channels
#define F1 128        // layer1 out = heads*hid = 4*32
#define H  4          // layer1 heads
#define F2 64         // layer2 out channels

// ---------------- device scratch ----------------
__device__ __half g_h1h[NN * F1];   // layer1 node features, fp16 (gather payload)
__device__ float g_as1[NN * H];
__device__ float g_ad1[NN * H];
__device__ float g_out1[NN * F1];   // layer1 output, normalized + bias + elu (fp32)
__device__ __half g_h2h[NN * F2];   // layer2 node features, fp16
__device__ float g_as2[NN];
__device__ float g_ad2[NN];
__device__ int   g_cnt[NN];         // degree histogram / scatter counters
__device__ int   g_rowptr[NN + 1];
__device__ int   g_csrc[NE];        // src ids sorted by dst (CSR)

// ---------------- helpers ----------------
__device__ __forceinline__ float lrexp(float t) {
    t = t > 0.f ? t : 0.2f * t;      // LeakyReLU(0.2)
    return __expf(t);
}

__device__ __forceinline__ int detect_is64(const int* __restrict__ raw) {
    int nz = 0;
#pragma unroll
    for (int k = 0; k < 64; k++) nz |= raw[2 * (k * 631) + 1];
    return (nz == 0) ? 1 : 0;
}

// ---------------- CSR build ----------------
__global__ void zero_cnt() {
    int i = blockIdx.x * blockDim.x + threadIdx.x;
    if (i < NN) g_cnt[i] = 0;
}

__global__ void hist_edges(const int* __restrict__ raw) {
    __shared__ int s_is64;
    if (threadIdx.x == 0) s_is64 = detect_is64(raw);
    __syncthreads();
    int i = blockIdx.x * blockDim.x + threadIdx.x;
    if (i >= NE) return;
    int d = s_is64 ? reinterpret_cast<const int2*>(raw)[NE + i].x : raw[NE + i];
    atomicAdd(&g_cnt[d], 1);
}

// single-block exclusive scan over 50k degrees -> rowptr; resets cnt to 0
__global__ void scan_rowptr() {
    __shared__ int ssum[1024];
    const int t = threadIdx.x;
    const int CH = (NN + 1023) / 1024;   // 49
    const int base = t * CH;
    int local = 0;
    for (int i = 0; i < CH; i++) {
        int idx = base + i;
        if (idx < NN) local += g_cnt[idx];
    }
    ssum[t] = local;
    __syncthreads();
    for (int off = 1; off < 1024; off <<= 1) {
        int v = (t >= off) ? ssum[t - off] : 0;
        __syncthreads();
        ssum[t] += v;
        __syncthreads();
    }
    int run = (t > 0) ? ssum[t - 1] : 0;   // exclusive prefix
    for (int i = 0; i < CH; i++) {
        int idx = base + i;
        if (idx < NN) {
            int c = g_cnt[idx];
            g_rowptr[idx] = run;
            run += c;
            g_cnt[idx] = 0;
        }
    }
    if (t == 1023) g_rowptr[NN] = run;     // == NE
}

__global__ void scatter_edges(const int* __restrict__ raw) {
    __shared__ int s_is64;
    if (threadIdx.x == 0) s_is64 = detect_is64(raw);
    __syncthreads();
    int i = blockIdx.x * blockDim.x + threadIdx.x;
    if (i >= NE) return;
    int s, d;
    if (s_is64) {
        s = reinterpret_cast<const int2*>(raw)[i].x;
        d = reinterpret_cast<const int2*>(raw)[NE + i].x;
    } else {
        s = raw[i];
        d = raw[NE + i];
    }
    int pos = g_rowptr[d] + atomicAdd(&g_cnt[d], 1);
    g_csrc[pos] = s;
}

// ---------------- SGEMM + fused attention-coefficient epilogue ----------------
// C is written in fp16 (g_h1h / g_h2h); attention coeffs computed from fp32 acc.
template <int BM, int BN, int BK, int TM, int TN, int LAYER>
__global__ void __launch_bounds__((BM / TM) * (BN / TN), 2)
sgemm(const float* __restrict__ Ain, const float* __restrict__ B,
      const float* __restrict__ attS, const float* __restrict__ attD, int M) {
    constexpr int K = 128;
    constexpr int NT = (BM / TM) * (BN / TN);
    constexpr int A_IT = BM * BK / (4 * NT);
    constexpr int B_IT = BK * BN / (4 * NT);
    const float* A = (LAYER == 1) ? Ain : g_out1;
    __half* C      = (LAYER == 1) ? g_h1h : g_h2h;

    __shared__ __align__(16) float As[2][BK][BM];   // transposed: As[k][m]
    __shared__ __align__(16) float Bs[2][BK][BN];

    const int tid  = threadIdx.x;
    const int trow = tid / (BN / TN);
    const int tcol = tid % (BN / TN);
    const int rowBase = blockIdx.x * BM;

    float4 aReg[A_IT], bReg[B_IT];

    auto gload = [&](int k0) {
#pragma unroll
        for (int it = 0; it < A_IT; it++) {
            int i = (tid + it * NT) * 4;
            int r = i / BK, c = i % BK;
            int gr = rowBase + r;
            float4 v = make_float4(0.f, 0.f, 0.f, 0.f);
            if (gr < M) v = *reinterpret_cast<const float4*>(&A[(long)gr * K + k0 + c]);
            aReg[it] = v;
        }
#pragma unroll
        for (int it = 0; it < B_IT; it++) {
            int i = (tid + it * NT) * 4;
            int r = i / BN, c = i % BN;
            bReg[it] = *reinterpret_cast<const float4*>(&B[(long)(k0 + r) * BN + c]);
        }
    };

    auto sstore = [&](int buf) {
#pragma unroll
        for (int it = 0; it < A_IT; it++) {
            int i = (tid + it * NT) * 4;
            int r = i / BK, c = i % BK;
            As[buf][c + 0][r] = aReg[it].x;
            As[buf][c + 1][r] = aReg[it].y;
            As[buf][c + 2][r] = aReg[it].z;
            As[buf][c + 3][r] = aReg[it].w;
        }
#pragma unroll
        for (int it = 0; it < B_IT; it++) {
            int i = (tid + it * NT) * 4;
            int r = i / BN, c = i % BN;
            *reinterpret_cast<float4*>(&Bs[buf][r][c]) = bReg[it];
        }
    };

    float acc[TM][TN];
#pragma unroll
    for (int m = 0; m < TM; m++)
#pragma unroll
        for (int n = 0; n < TN; n++) acc[m][n] = 0.f;

    auto compute = [&](int buf) {
#pragma unroll
        for (int k = 0; k < BK; k++) {
            float ra[TM], rb[TN];
#pragma unroll
            for (int m = 0; m < TM; m += 4)
                *reinterpret_cast<float4*>(&ra[m]) =
                    *reinterpret_cast<const float4*>(&As[buf][k][trow * TM + m]);
#pragma unroll
            for (int n = 0; n < TN; n += 4)
                *reinterpret_cast<float4*>(&rb[n]) =
                    *reinterpret_cast<const float4*>(&Bs[buf][k][tcol * TN + n]);
#pragma unroll
            for (int m = 0; m < TM; m++)
#pragma unroll
                for (int n = 0; n < TN; n++)
                    acc[m][n] = fmaf(ra[m], rb[n], acc[m][n]);
        }
    };

    gload(0);
    sstore(0);
    __syncthreads();
    int buf = 0;
    for (int k0 = BK; k0 < K; k0 += BK) {
        gload(k0);
        compute(buf);
        sstore(buf ^ 1);
        __syncthreads();
        buf ^= 1;
    }
    compute(buf);

    // ---- write C tile in fp16 ----
#pragma unroll
    for (int m = 0; m < TM; m++) {
        int gr = rowBase + trow * TM + m;
        if (gr < M) {
            unsigned int packed[TN / 2];
#pragma unroll
            for (int n = 0; n < TN; n += 2) {
                __half2 h = __float22half2_rn(make_float2(acc[m][n], acc[m][n + 1]));
                packed[n / 2] = *reinterpret_cast<unsigned int*>(&h);
            }
            __half* dst = &C[(long)gr * BN + tcol * TN];
            if (TN == 8) {
                *reinterpret_cast<uint4*>(dst) =
                    make_uint4(packed[0], packed[1], packed[2], packed[3]);
            } else {
                *reinterpret_cast<uint2*>(dst) = make_uint2(packed[0], packed[1]);
            }
        }
    }

    // ---- fused attention epilogue (fp32 acc) ----
    float asr[TN], adr[TN];
#pragma unroll
    for (int n = 0; n < TN; n++) {
        asr[n] = attS[tcol * TN + n];
        adr[n] = attD[tcol * TN + n];
    }
    float pa[TM], pd[TM];
#pragma unroll
    for (int m = 0; m < TM; m++) {
        float a = 0.f, b = 0.f;
#pragma unroll
        for (int n = 0; n < TN; n++) {
            a = fmaf(acc[m][n], asr[n], a);
            b = fmaf(acc[m][n], adr[n], b);
        }
        if (LAYER == 1) {
            a += __shfl_down_sync(0xffffffffu, a, 2);
            a += __shfl_down_sync(0xffffffffu, a, 1);
            b += __shfl_down_sync(0xffffffffu, b, 2);
            b += __shfl_down_sync(0xffffffffu, b, 1);
        } else {
            a += __shfl_down_sync(0xffffffffu, a, 8);
            a += __shfl_down_sync(0xffffffffu, a, 4);
            a += __shfl_down_sync(0xffffffffu, a, 2);
            a += __shfl_down_sync(0xffffffffu, a, 1);
            b += __shfl_down_sync(0xffffffffu, b, 8);
            b += __shfl_down_sync(0xffffffffu, b, 4);
            b += __shfl_down_sync(0xffffffffu, b, 2);
            b += __shfl_down_sync(0xffffffffu, b, 1);
        }
        pa[m] = a;
        pd[m] = b;
    }

    float* sA = &Bs[0][0][0];
    float* sD = sA + BM * H;
    __syncthreads();

    if (LAYER == 1) {
        if ((tcol & 3) == 0) {
            int head = tcol >> 2;
#pragma unroll
            for (int m = 0; m < TM; m++) {
                sA[(trow * TM + m) * H + head] = pa[m];
                sD[(trow * TM + m) * H + head] = pd[m];
            }
        }
        __syncthreads();
        if (tid < BM) {
            int gr = rowBase + tid;
            if (gr < M) {
                *reinterpret_cast<float4*>(&g_as1[gr * H]) =
                    *reinterpret_cast<const float4*>(&sA[tid * H]);
                *reinterpret_cast<float4*>(&g_ad1[gr * H]) =
                    *reinterpret_cast<const float4*>(&sD[tid * H]);
            }
        }
    } else {
        if (tcol == 0) {
#pragma unroll
            for (int m = 0; m < TM; m++) {
                sA[trow * TM + m] = pa[m];
                sD[trow * TM + m] = pd[m];
            }
        }
        __syncthreads();
        if (tid < BM) {
            int gr = rowBase + tid;
            if (gr < M) {
                g_as2[gr] = sA[tid];
                g_ad2[gr] = sD[tid];
            }
        }
    }
}

// ---------------- layer-1 aggregation: one warp per dst node ----------------
__global__ void __launch_bounds__(256) agg1(const float* __restrict__ b1) {
    __shared__ __align__(16) float sp[8][32][4];   // staged p per head
    __shared__ int ssrc[8][32];
    const int wid  = threadIdx.x >> 5;
    const int lane = threadIdx.x & 31;
    const int n    = (blockIdx.x * blockDim.x + threadIdx.x) >> 5;
    if (n >= NN) return;
    const int beg = g_rowptr[n], end = g_rowptr[n + 1];
    const int head = lane >> 3;
    const float4 ad = *reinterpret_cast<const float4*>(&g_ad1[n * H]);
    const uint2* hp = reinterpret_cast<const uint2*>(g_h1h);   // 4 halves per uint2

    float4 sumv = make_float4(0.f, 0.f, 0.f, 0.f);
    float4 acc0 = make_float4(0.f, 0.f, 0.f, 0.f);
    float4 acc1 = make_float4(0.f, 0.f, 0.f, 0.f);

    for (int e0 = beg; e0 < end; e0 += 32) {
        const int m = min(32, end - e0);
        // ---- phase A: lane j handles edge e0+j ----
        float4 p4 = make_float4(0.f, 0.f, 0.f, 0.f);
        int s = 0;
        if (lane < m) {
            s = g_csrc[e0 + lane];
            float4 as = *reinterpret_cast<const float4*>(&g_as1[s * H]);
            p4.x = lrexp(as.x + ad.x);
            p4.y = lrexp(as.y + ad.y);
            p4.z = lrexp(as.z + ad.z);
            p4.w = lrexp(as.w + ad.w);
        }
        sumv.x += p4.x; sumv.y += p4.y; sumv.z += p4.z; sumv.w += p4.w;
        *reinterpret_cast<float4*>(&sp[wid][lane][0]) = p4;
        ssrc[wid][lane] = s;
        __syncwarp();
        // ---- phase B: unroll-2 fp16 gather (8B per lane per edge) ----
        int j = 0;
        for (; j + 2 <= m; j += 2) {
            int s0 = ssrc[wid][j + 0];
            int s1 = ssrc[wid][j + 1];
            float a0 = sp[wid][j + 0][head];
            float a1 = sp[wid][j + 1][head];
            uint2 r0 = hp[s0 * (F1 / 4) + lane];
            uint2 r1 = hp[s1 * (F1 / 4) + lane];
            float2 f00 = __half22float2(*reinterpret_cast<__half2*>(&r0.x));
            float2 f01 = __half22float2(*reinterpret_cast<__half2*>(&r0.y));
            float2 f10 = __half22float2(*reinterpret_cast<__half2*>(&r1.x));
            float2 f11 = __half22float2(*reinterpret_cast<__half2*>(&r1.y));
            acc0.x = fmaf(a0, f00.x, acc0.x); acc0.y = fmaf(a0, f00.y, acc0.y);
            acc0.z = fmaf(a0, f01.x, acc0.z); acc0.w = fmaf(a0, f01.y, acc0.w);
            acc1.x = fmaf(a1, f10.x, acc1.x); acc1.y = fmaf(a1, f10.y, acc1.y);
            acc1.z = fmaf(a1, f11.x, acc1.z); acc1.w = fmaf(a1, f11.y, acc1.w);
        }
        if (j < m) {
            int s0 = ssrc[wid][j];
            float a0 = sp[wid][j][head];
            uint2 r0 = hp[s0 * (F1 / 4) + lane];
            float2 f00 = __half22float2(*reinterpret_cast<__half2*>(&r0.x));
            float2 f01 = __half22float2(*reinterpret_cast<__half2*>(&r0.y));
            acc0.x = fmaf(a0, f00.x, acc0.x); acc0.y = fmaf(a0, f00.y, acc0.y);
            acc0.z = fmaf(a0, f01.x, acc0.z); acc0.w = fmaf(a0, f01.y, acc0.w);
        }
        __syncwarp();
    }

    float4 acc;
    acc.x = acc0.x + acc1.x;
    acc.y = acc0.y + acc1.y;
    acc.z = acc0.z + acc1.z;
    acc.w = acc0.w + acc1.w;

#pragma unroll
    for (int o = 16; o > 0; o >>= 1) {
        sumv.x += __shfl_xor_sync(0xffffffffu, sumv.x, o);
        sumv.y += __shfl_xor_sync(0xffffffffu, sumv.y, o);
        sumv.z += __shfl_xor_sync(0xffffffffu, sumv.z, o);
        sumv.w += __shfl_xor_sync(0xffffffffu, sumv.w, o);
    }
    float sump = head == 0 ? sumv.x : head == 1 ? sumv.y : head == 2 ? sumv.z : sumv.w;
    float inv = 1.f / (sump + 1e-16f);
    float4 bb = *reinterpret_cast<const float4*>(&b1[lane * 4]);
    float4 o;
    o.x = acc.x * inv + bb.x; o.x = o.x > 0.f ? o.x : expm1f(o.x);
    o.y = acc.y * inv + bb.y; o.y = o.y > 0.f ? o.y : expm1f(o.y);
    o.z = acc.z * inv + bb.z; o.z = o.z > 0.f ? o.z : expm1f(o.z);
    o.w = acc.w * inv + bb.w; o.w = o.w > 0.f ? o.w : expm1f(o.w);
    *reinterpret_cast<float4*>(&g_out1[n * F1 + lane * 4]) = o;
}

// ---------------- layer-2 aggregation: one warp per dst node ----------------
__global__ void __launch_bounds__(256) agg2(float* __restrict__ out, const float* __restrict__ b2) {
    __shared__ float sp[8][32];
    __shared__ int ssrc[8][32];
    const int wid  = threadIdx.x >> 5;
    const int lane = threadIdx.x & 31;
    const int n    = (blockIdx.x * blockDim.x + threadIdx.x) >> 5;
    if (n >= NN) return;
    const int beg = g_rowptr[n], end = g_rowptr[n + 1];
    const float ad = g_ad2[n];
    const unsigned int* hp = reinterpret_cast<const unsigned int*>(g_h2h); // 2 halves/uint

    float sump = 0.f;
    float2 acc0 = make_float2(0.f, 0.f);
    float2 acc1 = make_float2(0.f, 0.f);

    for (int e0 = beg; e0 < end; e0 += 32) {
        const int m = min(32, end - e0);
        float p = 0.f;
        int s = 0;
        if (lane < m) {
            s = g_csrc[e0 + lane];
            p = lrexp(g_as2[s] + ad);
        }
        sump += p;
        sp[wid][lane] = p;
        ssrc[wid][lane] = s;
        __syncwarp();
        int j = 0;
        for (; j + 2 <= m; j += 2) {
            int s0 = ssrc[wid][j + 0];
            int s1 = ssrc[wid][j + 1];
            float a0 = sp[wid][j + 0];
            float a1 = sp[wid][j + 1];
            unsigned int r0 = hp[s0 * (F2 / 2) + lane];
            unsigned int r1 = hp[s1 * (F2 / 2) + lane];
            float2 f0 = __half22float2(*reinterpret_cast<__half2*>(&r0));
            float2 f1 = __half22float2(*reinterpret_cast<__half2*>(&r1));
            acc0.x = fmaf(a0, f0.x, acc0.x); acc0.y = fmaf(a0, f0.y, acc0.y);
            acc1.x = fmaf(a1, f1.x, acc1.x); acc1.y = fmaf(a1, f1.y, acc1.y);
        }
        if (j < m) {
            int s0 = ssrc[wid][j];
            float a0 = sp[wid][j];
            unsigned int r0 = hp[s0 * (F2 / 2) + lane];
            float2 f0 = __half22float2(*reinterpret_cast<__half2*>(&r0));
            acc0.x = fmaf(a0, f0.x, acc0.x); acc0.y = fmaf(a0, f0.y, acc0.y);
        }
        __syncwarp();
    }

    float2 acc;
    acc.x = acc0.x + acc1.x;
    acc.y = acc0.y + acc1.y;
#pragma unroll
    for (int o = 16; o > 0; o >>= 1)
        sump += __shfl_xor_sync(0xffffffffu, sump, o);
    float inv = 1.f / (sump + 1e-16f);
    float2 o;
    o.x = acc.x * inv + b2[lane * 2];
    o.y = acc.y * inv + b2[lane * 2 + 1];
    *reinterpret_cast<float2*>(&out[n * F2 + lane * 2]) = o;
}

// ---------------- launch ----------------
extern "C" void kernel_launch(void* const* d_in, const int* in_sizes, int n_in,
                              void* d_out, int out_size) {
    const float* x        = (const float*)d_in[0];
    const int*   ei_raw   = (const int*)d_in[1];
    const float* W1       = (const float*)d_in[2];
    const float* att_src1 = (const float*)d_in[3];
    const float* att_dst1 = (const float*)d_in[4];
    const float* b1       = (const float*)d_in[5];
    const float* W2       = (const float*)d_in[6];
    const float* att_src2 = (const float*)d_in[7];
    const float* att_dst2 = (const float*)d_in[8];
    const float* b2       = (const float*)d_in[9];
    float* out = (float*)d_out;

    static cudaStream_t sCsr = nullptr;
    static cudaEvent_t evFork = nullptr, evJoin = nullptr;
    if (sCsr == nullptr) {
        cudaStreamCreateWithFlags(&sCsr, cudaStreamNonBlocking);
        cudaEventCreateWithFlags(&evFork, cudaEventDisableTiming);
        cudaEventCreateWithFlags(&evJoin, cudaEventDisableTiming);
    }

    // ---- fork first (empty default stream), then sgemm1 so CSR overlaps it ----
    cudaEventRecord(evFork, 0);
    cudaStreamWaitEvent(sCsr, evFork, 0);

    // layer 1 GEMM + att epilogue (default stream) — submitted first
    sgemm<128, 128, 16, 8, 8, 1><<<(NN + 127) / 128, 256>>>(x, W1, att_src1, att_dst1, NN);

    // CSR build chain on sCsr, concurrent with layer-1 GEMM
    zero_cnt<<<(NN + 255) / 256, 256, 0, sCsr>>>();
    hist_edges<<<(NE + 255) / 256, 256, 0, sCsr>>>(ei_raw);
    scan_rowptr<<<1, 1024, 0, sCsr>>>();
    scatter_edges<<<(NE + 255) / 256, 256, 0, sCsr>>>(ei_raw);
    cudaEventRecord(evJoin, sCsr);

    // ---- join, then aggregation ----
    cudaStreamWaitEvent(0, evJoin, 0);
    agg1<<<(NN * 32 + 255) / 256, 256>>>(b1);

    // ---- layer 2 ----
    sgemm<128, 64, 16, 8, 4, 2><<<(NN + 127) / 128, 256>>>(nullptr, W2, att_src2, att_dst2, NN);
    agg2<<<(NN * 32 + 255) / 256, 256>>>(out, b2);
}

// round 7
// speedup vs baseline: 2.2911x; 1.4160x over previous
#include <cuda_runtime.h>
#include <cuda_fp16.h>

// ---------------- problem constants ----------------
#define NN 50000      // nodes
#define NE 800000     // edges
#define IC 128        // input channels
#define F1 128        // layer1 out = heads*hid = 4*32
#define H  4          // layer1 heads
#define F2 64         // layer2 out channels
#define SCAN_B 1024
#define NBLK ((NN + SCAN_B - 1) / SCAN_B)   // 49

// ---------------- device scratch ----------------
__device__ __half g_h1h[NN * F1];   // layer1 node features, fp16 (gather payload)
__device__ float g_as1[NN * H];
__device__ float g_ad1[NN * H];
__device__ float g_out1[NN * F1];   // layer1 output, normalized + bias + elu (fp32)
__device__ __half g_h2h[NN * F2];   // layer2 node features, fp16
__device__ float g_as2[NN];
__device__ float g_ad2[NN];
__device__ int   g_cnt[NN];         // degree histogram / scatter counters
__device__ int   g_rowptr[NN + 1];
__device__ int   g_csrc[NE];        // src ids sorted by dst (CSR)
__device__ int   g_bsum[NBLK];
__device__ int   g_boff[NBLK];

// ---------------- helpers ----------------
__device__ __forceinline__ float lrexp(float t) {
    t = t > 0.f ? t : 0.2f * t;      // LeakyReLU(0.2)
    return __expf(t);
}

__device__ __forceinline__ int detect_is64(const int* __restrict__ raw) {
    int nz = 0;
#pragma unroll
    for (int k = 0; k < 64; k++) nz |= raw[2 * (k * 631) + 1];
    return (nz == 0) ? 1 : 0;
}

// ---------------- CSR build ----------------
__global__ void zero_cnt() {
    int i = blockIdx.x * blockDim.x + threadIdx.x;
    if (i < NN) g_cnt[i] = 0;
}

__global__ void hist_edges(const int* __restrict__ raw) {
    __shared__ int s_is64;
    if (threadIdx.x == 0) s_is64 = detect_is64(raw);
    __syncthreads();
    int i = blockIdx.x * blockDim.x + threadIdx.x;
    if (i >= NE) return;
    int d = s_is64 ? reinterpret_cast<const int2*>(raw)[NE + i].x : raw[NE + i];
    atomicAdd(&g_cnt[d], 1);
}

// ---- multi-block exclusive scan: A) block sums ----
__global__ void scanA() {
    __shared__ int s[32];
    int idx = blockIdx.x * SCAN_B + threadIdx.x;
    int v = (idx < NN) ? g_cnt[idx] : 0;
#pragma unroll
    for (int o = 16; o > 0; o >>= 1) v += __shfl_down_sync(0xffffffffu, v, o);
    if ((threadIdx.x & 31) == 0) s[threadIdx.x >> 5] = v;
    __syncthreads();
    if (threadIdx.x < 32) {
        int u = s[threadIdx.x];
#pragma unroll
        for (int o = 16; o > 0; o >>= 1) u += __shfl_down_sync(0xffffffffu, u, o);
        if (threadIdx.x == 0) g_bsum[blockIdx.x] = u;
    }
}

// ---- B) scan 49 block sums (1 block, 64 threads) ----
__global__ void scanB() {
    __shared__ int s[64];
    int t = threadIdx.x;
    int v = (t < NBLK) ? g_bsum[t] : 0;
    s[t] = v;
    __syncthreads();
#pragma unroll
    for (int off = 1; off < 64; off <<= 1) {
        int u = (t >= off) ? s[t - off] : 0;
        __syncthreads();
        s[t] += u;
        __syncthreads();
    }
    if (t < NBLK) g_boff[t] = s[t] - v;   // exclusive
}

// ---- C) per-block local scan + offset -> rowptr; resets cnt ----
__global__ void scanC() {
    __shared__ int s[SCAN_B];
    int t = threadIdx.x;
    int idx = blockIdx.x * SCAN_B + t;
    int v = (idx < NN) ? g_cnt[idx] : 0;
    s[t] = v;
    __syncthreads();
    for (int off = 1; off < SCAN_B; off <<= 1) {
        int u = (t >= off) ? s[t - off] : 0;
        __syncthreads();
        s[t] += u;
        __syncthreads();
    }
    int excl = s[t] - v + g_boff[blockIdx.x];
    if (idx < NN) {
        g_rowptr[idx] = excl;
        g_cnt[idx] = 0;
    }
    if (idx == NN - 1) g_rowptr[NN] = excl + v;
}

__global__ void scatter_edges(const int* __restrict__ raw) {
    __shared__ int s_is64;
    if (threadIdx.x == 0) s_is64 = detect_is64(raw);
    __syncthreads();
    int i = blockIdx.x * blockDim.x + threadIdx.x;
    if (i >= NE) return;
    int s, d;
    if (s_is64) {
        s = reinterpret_cast<const int2*>(raw)[i].x;
        d = reinterpret_cast<const int2*>(raw)[NE + i].x;
    } else {
        s = raw[i];
        d = raw[NE + i];
    }
    int pos = g_rowptr[d] + atomicAdd(&g_cnt[d], 1);
    g_csrc[pos] = s;
}

// ---------------- SGEMM + fused attention-coefficient epilogue ----------------
template <int BM, int BN, int BK, int TM, int TN, int LAYER>
__global__ void __launch_bounds__((BM / TM) * (BN / TN), 2)
sgemm(const float* __restrict__ Ain, const float* __restrict__ B,
      const float* __restrict__ attS, const float* __restrict__ attD, int M) {
    constexpr int K = 128;
    constexpr int NT = (BM / TM) * (BN / TN);
    constexpr int A_IT = BM * BK / (4 * NT);
    constexpr int B_IT = BK * BN / (4 * NT);
    const float* A = (LAYER == 1) ? Ain : g_out1;
    __half* C      = (LAYER == 1) ? g_h1h : g_h2h;

    __shared__ __align__(16) float As[2][BK][BM];   // transposed: As[k][m]
    __shared__ __align__(16) float Bs[2][BK][BN];

    const int tid  = threadIdx.x;
    const int trow = tid / (BN / TN);
    const int tcol = tid % (BN / TN);
    const int rowBase = blockIdx.x * BM;

    float4 aReg[A_IT], bReg[B_IT];

    auto gload = [&](int k0) {
#pragma unroll
        for (int it = 0; it < A_IT; it++) {
            int i = (tid + it * NT) * 4;
            int r = i / BK, c = i % BK;
            int gr = rowBase + r;
            float4 v = make_float4(0.f, 0.f, 0.f, 0.f);
            if (gr < M) v = *reinterpret_cast<const float4*>(&A[(long)gr * K + k0 + c]);
            aReg[it] = v;
        }
#pragma unroll
        for (int it = 0; it < B_IT; it++) {
            int i = (tid + it * NT) * 4;
            int r = i / BN, c = i % BN;
            bReg[it] = *reinterpret_cast<const float4*>(&B[(long)(k0 + r) * BN + c]);
        }
    };

    auto sstore = [&](int buf) {
#pragma unroll
        for (int it = 0; it < A_IT; it++) {
            int i = (tid + it * NT) * 4;
            int r = i / BK, c = i % BK;
            As[buf][c + 0][r] = aReg[it].x;
            As[buf][c + 1][r] = aReg[it].y;
            As[buf][c + 2][r] = aReg[it].z;
            As[buf][c + 3][r] = aReg[it].w;
        }
#pragma unroll
        for (int it = 0; it < B_IT; it++) {
            int i = (tid + it * NT) * 4;
            int r = i / BN, c = i % BN;
            *reinterpret_cast<float4*>(&Bs[buf][r][c]) = bReg[it];
        }
    };

    float acc[TM][TN];
#pragma unroll
    for (int m = 0; m < TM; m++)
#pragma unroll
        for (int n = 0; n < TN; n++) acc[m][n] = 0.f;

    auto compute = [&](int buf) {
#pragma unroll
        for (int k = 0; k < BK; k++) {
            float ra[TM], rb[TN];
#pragma unroll
            for (int m = 0; m < TM; m += 4)
                *reinterpret_cast<float4*>(&ra[m]) =
                    *reinterpret_cast<const float4*>(&As[buf][k][trow * TM + m]);
#pragma unroll
            for (int n = 0; n < TN; n += 4)
                *reinterpret_cast<float4*>(&rb[n]) =
                    *reinterpret_cast<const float4*>(&Bs[buf][k][tcol * TN + n]);
#pragma unroll
            for (int m = 0; m < TM; m++)
#pragma unroll
                for (int n = 0; n < TN; n++)
                    acc[m][n] = fmaf(ra[m], rb[n], acc[m][n]);
        }
    };

    gload(0);
    sstore(0);
    __syncthreads();
    int buf = 0;
    for (int k0 = BK; k0 < K; k0 += BK) {
        gload(k0);
        compute(buf);
        sstore(buf ^ 1);
        __syncthreads();
        buf ^= 1;
    }
    compute(buf);

    // ---- write C tile in fp16 ----
#pragma unroll
    for (int m = 0; m < TM; m++) {
        int gr = rowBase + trow * TM + m;
        if (gr < M) {
            unsigned int packed[TN / 2];
#pragma unroll
            for (int n = 0; n < TN; n += 2) {
                __half2 h = __float22half2_rn(make_float2(acc[m][n], acc[m][n + 1]));
                packed[n / 2] = *reinterpret_cast<unsigned int*>(&h);
            }
            __half* dst = &C[(long)gr * BN + tcol * TN];
            if (TN == 8) {
                *reinterpret_cast<uint4*>(dst) =
                    make_uint4(packed[0], packed[1], packed[2], packed[3]);
            } else {
                *reinterpret_cast<uint2*>(dst) = make_uint2(packed[0], packed[1]);
            }
        }
    }

    // ---- fused attention epilogue (fp32 acc) ----
    float asr[TN], adr[TN];
#pragma unroll
    for (int n = 0; n < TN; n++) {
        asr[n] = attS[tcol * TN + n];
        adr[n] = attD[tcol * TN + n];
    }
    float pa[TM], pd[TM];
#pragma unroll
    for (int m = 0; m < TM; m++) {
        float a = 0.f, b = 0.f;
#pragma unroll
        for (int n = 0; n < TN; n++) {
            a = fmaf(acc[m][n], asr[n], a);
            b = fmaf(acc[m][n], adr[n], b);
        }
        if (LAYER == 1) {
            a += __shfl_down_sync(0xffffffffu, a, 2);
            a += __shfl_down_sync(0xffffffffu, a, 1);
            b += __shfl_down_sync(0xffffffffu, b, 2);
            b += __shfl_down_sync(0xffffffffu, b, 1);
        } else {
            a += __shfl_down_sync(0xffffffffu, a, 8);
            a += __shfl_down_sync(0xffffffffu, a, 4);
            a += __shfl_down_sync(0xffffffffu, a, 2);
            a += __shfl_down_sync(0xffffffffu, a, 1);
            b += __shfl_down_sync(0xffffffffu, b, 8);
            b += __shfl_down_sync(0xffffffffu, b, 4);
            b += __shfl_down_sync(0xffffffffu, b, 2);
            b += __shfl_down_sync(0xffffffffu, b, 1);
        }
        pa[m] = a;
        pd[m] = b;
    }

    float* sA = &Bs[0][0][0];
    float* sD = sA + BM * H;
    __syncthreads();

    if (LAYER == 1) {
        if ((tcol & 3) == 0) {
            int head = tcol >> 2;
#pragma unroll
            for (int m = 0; m < TM; m++) {
                sA[(trow * TM + m) * H + head] = pa[m];
                sD[(trow * TM + m) * H + head] = pd[m];
            }
        }
        __syncthreads();
        if (tid < BM) {
            int gr = rowBase + tid;
            if (gr < M) {
                *reinterpret_cast<float4*>(&g_as1[gr * H]) =
                    *reinterpret_cast<const float4*>(&sA[tid * H]);
                *reinterpret_cast<float4*>(&g_ad1[gr * H]) =
                    *reinterpret_cast<const float4*>(&sD[tid * H]);
            }
        }
    } else {
        if (tcol == 0) {
#pragma unroll
            for (int m = 0; m < TM; m++) {
                sA[trow * TM + m] = pa[m];
                sD[trow * TM + m] = pd[m];
            }
        }
        __syncthreads();
        if (tid < BM) {
            int gr = rowBase + tid;
            if (gr < M) {
                g_as2[gr] = sA[tid];
                g_ad2[gr] = sD[tid];
            }
        }
    }
}

// ---------------- layer-1 aggregation: one warp per dst node ----------------
__global__ void __launch_bounds__(256) agg1(const float* __restrict__ b1) {
    __shared__ __align__(16) float sp[8][32][4];   // staged p per head
    __shared__ int ssrc[8][32];
    const int wid  = threadIdx.x >> 5;
    const int lane = threadIdx.x & 31;
    const int n    = (blockIdx.x * blockDim.x + threadIdx.x) >> 5;
    if (n >= NN) return;
    const int beg = g_rowptr[n], end = g_rowptr[n + 1];
    const int head = lane >> 3;
    const float4 ad = *reinterpret_cast<const float4*>(&g_ad1[n * H]);
    const uint2* hp = reinterpret_cast<const uint2*>(g_h1h);   // 4 halves per uint2

    float4 sumv = make_float4(0.f, 0.f, 0.f, 0.f);
    float4 acc0 = make_float4(0.f, 0.f, 0.f, 0.f);
    float4 acc1 = make_float4(0.f, 0.f, 0.f, 0.f);

    for (int e0 = beg; e0 < end; e0 += 32) {
        const int m = min(32, end - e0);
        float4 p4 = make_float4(0.f, 0.f, 0.f, 0.f);
        int s = 0;
        if (lane < m) {
            s = g_csrc[e0 + lane];
            float4 as = *reinterpret_cast<const float4*>(&g_as1[s * H]);
            p4.x = lrexp(as.x + ad.x);
            p4.y = lrexp(as.y + ad.y);
            p4.z = lrexp(as.z + ad.z);
            p4.w = lrexp(as.w + ad.w);
        }
        sumv.x += p4.x; sumv.y += p4.y; sumv.z += p4.z; sumv.w += p4.w;
        *reinterpret_cast<float4*>(&sp[wid][lane][0]) = p4;
        ssrc[wid][lane] = s;
        __syncwarp();
        int j = 0;
        for (; j + 2 <= m; j += 2) {
            int s0 = ssrc[wid][j + 0];
            int s1 = ssrc[wid][j + 1];
            float a0 = sp[wid][j + 0][head];
            float a1 = sp[wid][j + 1][head];
            uint2 r0 = hp[s0 * (F1 / 4) + lane];
            uint2 r1 = hp[s1 * (F1 / 4) + lane];
            float2 f00 = __half22float2(*reinterpret_cast<__half2*>(&r0.x));
            float2 f01 = __half22float2(*reinterpret_cast<__half2*>(&r0.y));
            float2 f10 = __half22float2(*reinterpret_cast<__half2*>(&r1.x));
            float2 f11 = __half22float2(*reinterpret_cast<__half2*>(&r1.y));
            acc0.x = fmaf(a0, f00.x, acc0.x); acc0.y = fmaf(a0, f00.y, acc0.y);
            acc0.z = fmaf(a0, f01.x, acc0.z); acc0.w = fmaf(a0, f01.y, acc0.w);
            acc1.x = fmaf(a1, f10.x, acc1.x); acc1.y = fmaf(a1, f10.y, acc1.y);
            acc1.z = fmaf(a1, f11.x, acc1.z); acc1.w = fmaf(a1, f11.y, acc1.w);
        }
        if (j < m) {
            int s0 = ssrc[wid][j];
            float a0 = sp[wid][j][head];
            uint2 r0 = hp[s0 * (F1 / 4) + lane];
            float2 f00 = __half22float2(*reinterpret_cast<__half2*>(&r0.x));
            float2 f01 = __half22float2(*reinterpret_cast<__half2*>(&r0.y));
            acc0.x = fmaf(a0, f00.x, acc0.x); acc0.y = fmaf(a0, f00.y, acc0.y);
            acc0.z = fmaf(a0, f01.x, acc0.z); acc0.w = fmaf(a0, f01.y, acc0.w);
        }
        __syncwarp();
    }

    float4 acc;
    acc.x = acc0.x + acc1.x;
    acc.y = acc0.y + acc1.y;
    acc.z = acc0.z + acc1.z;
    acc.w = acc0.w + acc1.w;

#pragma unroll
    for (int o = 16; o > 0; o >>= 1) {
        sumv.x += __shfl_xor_sync(0xffffffffu, sumv.x, o);
        sumv.y += __shfl_xor_sync(0xffffffffu, sumv.y, o);
        sumv.z += __shfl_xor_sync(0xffffffffu, sumv.z, o);
        sumv.w += __shfl_xor_sync(0xffffffffu, sumv.w, o);
    }
    float sump = head == 0 ? sumv.x : head == 1 ? sumv.y : head == 2 ? sumv.z : sumv.w;
    float inv = 1.f / (sump + 1e-16f);
    float4 bb = *reinterpret_cast<const float4*>(&b1[lane * 4]);
    float4 o;
    o.x = acc.x * inv + bb.x; o.x = o.x > 0.f ? o.x : expm1f(o.x);
    o.y = acc.y * inv + bb.y; o.y = o.y > 0.f ? o.y : expm1f(o.y);
    o.z = acc.z * inv + bb.z; o.z = o.z > 0.f ? o.z : expm1f(o.z);
    o.w = acc.w * inv + bb.w; o.w = o.w > 0.f ? o.w : expm1f(o.w);
    *reinterpret_cast<float4*>(&g_out1[n * F1 + lane * 4]) = o;
}

// ---------------- layer-2 aggregation: one warp per dst node ----------------
__global__ void __launch_bounds__(256) agg2(float* __restrict__ out, const float* __restrict__ b2) {
    __shared__ float sp[8][32];
    __shared__ int ssrc[8][32];
    const int wid  = threadIdx.x >> 5;
    const int lane = threadIdx.x & 31;
    const int n    = (blockIdx.x * blockDim.x + threadIdx.x) >> 5;
    if (n >= NN) return;
    const int beg = g_rowptr[n], end = g_rowptr[n + 1];
    const float ad = g_ad2[n];
    const unsigned int* hp = reinterpret_cast<const unsigned int*>(g_h2h); // 2 halves/uint

    float sump = 0.f;
    float2 acc0 = make_float2(0.f, 0.f);
    float2 acc1 = make_float2(0.f, 0.f);

    for (int e0 = beg; e0 < end; e0 += 32) {
        const int m = min(32, end - e0);
        float p = 0.f;
        int s = 0;
        if (lane < m) {
            s = g_csrc[e0 + lane];
            p = lrexp(g_as2[s] + ad);
        }
        sump += p;
        sp[wid][lane] = p;
        ssrc[wid][lane] = s;
        __syncwarp();
        int j = 0;
        for (; j + 2 <= m; j += 2) {
            int s0 = ssrc[wid][j + 0];
            int s1 = ssrc[wid][j + 1];
            float a0 = sp[wid][j + 0];
            float a1 = sp[wid][j + 1];
            unsigned int r0 = hp[s0 * (F2 / 2) + lane];
            unsigned int r1 = hp[s1 * (F2 / 2) + lane];
            float2 f0 = __half22float2(*reinterpret_cast<__half2*>(&r0));
            float2 f1 = __half22float2(*reinterpret_cast<__half2*>(&r1));
            acc0.x = fmaf(a0, f0.x, acc0.x); acc0.y = fmaf(a0, f0.y, acc0.y);
            acc1.x = fmaf(a1, f1.x, acc1.x); acc1.y = fmaf(a1, f1.y, acc1.y);
        }
        if (j < m) {
            int s0 = ssrc[wid][j];
            float a0 = sp[wid][j];
            unsigned int r0 = hp[s0 * (F2 / 2) + lane];
            float2 f0 = __half22float2(*reinterpret_cast<__half2*>(&r0));
            acc0.x = fmaf(a0, f0.x, acc0.x); acc0.y = fmaf(a0, f0.y, acc0.y);
        }
        __syncwarp();
    }

    float2 acc;
    acc.x = acc0.x + acc1.x;
    acc.y = acc0.y + acc1.y;
#pragma unroll
    for (int o = 16; o > 0; o >>= 1)
        sump += __shfl_xor_sync(0xffffffffu, sump, o);
    float inv = 1.f / (sump + 1e-16f);
    float2 o;
    o.x = acc.x * inv + b2[lane * 2];
    o.y = acc.y * inv + b2[lane * 2 + 1];
    *reinterpret_cast<float2*>(&out[n * F2 + lane * 2]) = o;
}

// ---------------- launch ----------------
extern "C" void kernel_launch(void* const* d_in, const int* in_sizes, int n_in,
                              void* d_out, int out_size) {
    const float* x        = (const float*)d_in[0];
    const int*   ei_raw   = (const int*)d_in[1];
    const float* W1       = (const float*)d_in[2];
    const float* att_src1 = (const float*)d_in[3];
    const float* att_dst1 = (const float*)d_in[4];
    const float* b1       = (const float*)d_in[5];
    const float* W2       = (const float*)d_in[6];
    const float* att_src2 = (const float*)d_in[7];
    const float* att_dst2 = (const float*)d_in[8];
    const float* b2       = (const float*)d_in[9];
    float* out = (float*)d_out;

    static cudaStream_t sCsr = nullptr;
    static cudaEvent_t evFork = nullptr, evJoin = nullptr;
    if (sCsr == nullptr) {
        cudaStreamCreateWithFlags(&sCsr, cudaStreamNonBlocking);
        cudaEventCreateWithFlags(&evFork, cudaEventDisableTiming);
        cudaEventCreateWithFlags(&evJoin, cudaEventDisableTiming);
    }

    cudaEventRecord(evFork, 0);
    cudaStreamWaitEvent(sCsr, evFork, 0);

    // layer 1 GEMM + att epilogue (default stream)
    sgemm<128, 128, 16, 8, 8, 1><<<(NN + 127) / 128, 256>>>(x, W1, att_src1, att_dst1, NN);

    // CSR build chain on sCsr, concurrent with layer-1 GEMM
    zero_cnt<<<(NN + 255) / 256, 256, 0, sCsr>>>();
    hist_edges<<<(NE + 255) / 256, 256, 0, sCsr>>>(ei_raw);
    scanA<<<NBLK, SCAN_B, 0, sCsr>>>();
    scanB<<<1, 64, 0, sCsr>>>();
    scanC<<<NBLK, SCAN_B, 0, sCsr>>>();
    scatter_edges<<<(NE + 255) / 256, 256, 0, sCsr>>>(ei_raw);
    cudaEventRecord(evJoin, sCsr);

    // ---- join, then aggregation ----
    cudaStreamWaitEvent(0, evJoin, 0);
    agg1<<<(NN * 32 + 255) / 256, 256>>>(b1);

    // ---- layer 2 ----
    sgemm<128, 64, 16, 8, 4, 2><<<(NN + 127) / 128, 256>>>(nullptr, W2, att_src2, att_dst2, NN);
    agg2<<<(NN * 32 + 255) / 256, 256>>>(out, b2);
}